// round 1
// baseline (speedup 1.0000x reference)
#include <cuda_runtime.h>
#include <math.h>

#define S_LEN  4096
#define DM     2048
#define NH     16
#define NKV    4
#define HD     128

// ---------------- scratch (device globals; no runtime alloc allowed) --------
__device__ float g_q[(size_t)S_LEN * DM];          // 32 MB  [s][h*128+d]
__device__ float g_k[(size_t)S_LEN * NKV * HD];    // 8 MB   [s][kvh*128+d]
__device__ float g_v[(size_t)S_LEN * NKV * HD];    // 8 MB
__device__ float g_attn[(size_t)S_LEN * DM];       // 32 MB  [s][h*128+d]

// ---------------- SGEMM: C[M,N] = A[M,K] * B[K,N], fp32 --------------------
// 128x128 tile, BK=8, 256 threads, 8x8 micro-tile. A transposed in smem.
__global__ __launch_bounds__(256) void sgemm_kernel(
    const float* __restrict__ A, const float* __restrict__ B,
    float* __restrict__ C, int M, int N, int K) {
  __shared__ float As[8][132];   // [k][m], padded
  __shared__ float Bs[8][132];   // [k][n], padded

  const int bm = blockIdx.y * 128;
  const int bn = blockIdx.x * 128;
  const int tid = threadIdx.x;
  const int tx = tid & 15, ty = tid >> 4;

  const int arow = tid >> 1;          // 0..127
  const int acol = (tid & 1) * 4;     // 0 or 4
  const int brow = tid >> 5;          // 0..7
  const int bcol = (tid & 31) * 4;    // 0..124

  const float* Ap = A + (size_t)(bm + arow) * K + acol;
  const float* Bp = B + (size_t)brow * N + bn + bcol;

  float acc[8][8];
#pragma unroll
  for (int i = 0; i < 8; i++)
#pragma unroll
    for (int j = 0; j < 8; j++) acc[i][j] = 0.0f;

  for (int k0 = 0; k0 < K; k0 += 8) {
    float4 a = *(const float4*)Ap; Ap += 8;
    float4 b = *(const float4*)Bp; Bp += (size_t)8 * N;
    __syncthreads();
    As[acol + 0][arow] = a.x;
    As[acol + 1][arow] = a.y;
    As[acol + 2][arow] = a.z;
    As[acol + 3][arow] = a.w;
    *(float4*)&Bs[brow][bcol] = b;
    __syncthreads();
#pragma unroll
    for (int kk = 0; kk < 8; kk++) {
      float4 a0 = *(const float4*)&As[kk][ty * 8];
      float4 a1 = *(const float4*)&As[kk][ty * 8 + 4];
      float4 b0 = *(const float4*)&Bs[kk][tx * 8];
      float4 b1 = *(const float4*)&Bs[kk][tx * 8 + 4];
      float av[8] = {a0.x, a0.y, a0.z, a0.w, a1.x, a1.y, a1.z, a1.w};
      float bv[8] = {b0.x, b0.y, b0.z, b0.w, b1.x, b1.y, b1.z, b1.w};
#pragma unroll
      for (int i = 0; i < 8; i++)
#pragma unroll
        for (int j = 0; j < 8; j++) acc[i][j] = fmaf(av[i], bv[j], acc[i][j]);
    }
  }

#pragma unroll
  for (int i = 0; i < 8; i++) {
    float* Cp = C + (size_t)(bm + ty * 8 + i) * N + bn + tx * 8;
    float4 c0 = {acc[i][0], acc[i][1], acc[i][2], acc[i][3]};
    float4 c1 = {acc[i][4], acc[i][5], acc[i][6], acc[i][7]};
    *(float4*)Cp = c0;
    *(float4*)(Cp + 4) = c1;
  }
}

// ---------------- RoPE -----------------------------------------------------
// grid (S, NH+NKV), block 64. Thread d rotates pair (d, d+64) of one head row.
__global__ void rope_kernel(float* __restrict__ q, float* __restrict__ k) {
  const int s = blockIdx.x;
  const int hh = blockIdx.y;
  const int d = threadIdx.x;   // 0..63
  float* ptr;
  if (hh < NH) ptr = q + (size_t)s * DM + hh * HD;
  else         ptr = k + (size_t)s * (NKV * HD) + (hh - NH) * HD;
  float inv = powf(10000.0f, -((float)(2 * d) / 128.0f));
  float ang = (float)s * inv;
  float sn, c;
  sincosf(ang, &sn, &c);
  float x0 = ptr[d];
  float x1 = ptr[d + 64];
  ptr[d]      = x0 * c - x1 * sn;
  ptr[d + 64] = x1 * c + x0 * sn;
}

// ---------------- Flash attention (causal, GQA) -----------------------------
#define BQ 128
#define BKV 64
#define QT_STR (BQ + 4)   // 132
#define KT_STR (BKV + 4)  // 68
#define V_STR  (HD + 4)   // 132
#define PT_STR (BQ + 4)   // 132
#define FLASH_SMEM ((HD * QT_STR + HD * KT_STR + BKV * V_STR + BKV * PT_STR) * 4)

__global__ __launch_bounds__(256, 1) void flash_kernel(
    const float* __restrict__ Q, const float* __restrict__ K,
    const float* __restrict__ V, float* __restrict__ O) {
  extern __shared__ float smem[];
  float* Qt = smem;                       // [HD][QT_STR]  (d-major, transposed)
  float* Kt = Qt + HD * QT_STR;           // [HD][KT_STR]
  float* Vs = Kt + HD * KT_STR;           // [BKV][V_STR]  (natural)
  float* Pt = Vs + BKV * V_STR;           // [BKV][PT_STR] (kv-major)

  const int h  = blockIdx.y;
  const int qb = gridDim.x - 1 - blockIdx.x;   // big blocks launch first
  const int q0 = qb * BQ;
  const int kvh = h >> 2;
  const int tid = threadIdx.x;
  const int tx = tid & 15, ty = tid >> 4;

  // Load Q tile transposed: Qt[d][m]
  for (int f = tid; f < BQ * (HD / 4); f += 256) {
    int m = f >> 5;
    int d4 = (f & 31) * 4;
    float4 v = *(const float4*)(Q + (size_t)(q0 + m) * DM + h * HD + d4);
    Qt[(d4 + 0) * QT_STR + m] = v.x;
    Qt[(d4 + 1) * QT_STR + m] = v.y;
    Qt[(d4 + 2) * QT_STR + m] = v.z;
    Qt[(d4 + 3) * QT_STR + m] = v.w;
  }

  float acc[8][8];
  float m_i[8], l_i[8];
#pragma unroll
  for (int i = 0; i < 8; i++) {
    m_i[i] = -3.0e38f;
    l_i[i] = 0.0f;
#pragma unroll
    for (int j = 0; j < 8; j++) acc[i][j] = 0.0f;
  }

  const int ntiles = (q0 + BQ) / BKV;
  const float scale = 0.08838834764831845f;  // 1/sqrt(128)

  for (int t = 0; t < ntiles; t++) {
    __syncthreads();
    // K tile transposed: Kt[d][n]
    for (int f = tid; f < BKV * (HD / 4); f += 256) {
      int n = f >> 5;
      int d4 = (f & 31) * 4;
      float4 v = *(const float4*)(K + (size_t)(t * BKV + n) * (NKV * HD) + kvh * HD + d4);
      Kt[(d4 + 0) * KT_STR + n] = v.x;
      Kt[(d4 + 1) * KT_STR + n] = v.y;
      Kt[(d4 + 2) * KT_STR + n] = v.z;
      Kt[(d4 + 3) * KT_STR + n] = v.w;
    }
    // V tile natural: Vs[n][d]
    for (int f = tid; f < BKV * (HD / 4); f += 256) {
      int n = f >> 5;
      int d4 = (f & 31) * 4;
      *(float4*)&Vs[n * V_STR + d4] =
          *(const float4*)(V + (size_t)(t * BKV + n) * (NKV * HD) + kvh * HD + d4);
    }
    __syncthreads();

    // scores S = Q * K^T  (128x64), thread: rows ty*8.., cols tx*4..
    float s[8][4];
#pragma unroll
    for (int i = 0; i < 8; i++)
#pragma unroll
      for (int j = 0; j < 4; j++) s[i][j] = 0.0f;
#pragma unroll 8
    for (int kk = 0; kk < HD; kk++) {
      float4 a0 = *(const float4*)&Qt[kk * QT_STR + ty * 8];
      float4 a1 = *(const float4*)&Qt[kk * QT_STR + ty * 8 + 4];
      float4 b  = *(const float4*)&Kt[kk * KT_STR + tx * 4];
      float av[8] = {a0.x, a0.y, a0.z, a0.w, a1.x, a1.y, a1.z, a1.w};
      float bv[4] = {b.x, b.y, b.z, b.w};
#pragma unroll
      for (int i = 0; i < 8; i++)
#pragma unroll
        for (int j = 0; j < 4; j++) s[i][j] = fmaf(av[i], bv[j], s[i][j]);
    }

    // mask + online softmax (row groups = 16 tx lanes, shuffle width 16)
    float p[8][4];
    float alpha[8];
#pragma unroll
    for (int i = 0; i < 8; i++) {
      const int qr = q0 + ty * 8 + i;
      float mx = -3.0e38f;
#pragma unroll
      for (int j = 0; j < 4; j++) {
        float sv = (t * BKV + tx * 4 + j <= qr) ? s[i][j] * scale : -3.0e38f;
        s[i][j] = sv;
        mx = fmaxf(mx, sv);
      }
#pragma unroll
      for (int o = 8; o >= 1; o >>= 1)
        mx = fmaxf(mx, __shfl_xor_sync(0xffffffffu, mx, o));
      const float mn = fmaxf(m_i[i], mx);
      float rs = 0.0f;
#pragma unroll
      for (int j = 0; j < 4; j++) {
        float pv = __expf(s[i][j] - mn);
        p[i][j] = pv;
        rs += pv;
      }
#pragma unroll
      for (int o = 8; o >= 1; o >>= 1)
        rs += __shfl_xor_sync(0xffffffffu, rs, o);
      alpha[i] = __expf(m_i[i] - mn);
      l_i[i] = l_i[i] * alpha[i] + rs;
      m_i[i] = mn;
    }
#pragma unroll
    for (int i = 0; i < 8; i++)
#pragma unroll
      for (int j = 0; j < 8; j++) acc[i][j] *= alpha[i];

    // P transposed to smem: Pt[n][m]
#pragma unroll
    for (int i = 0; i < 8; i++)
#pragma unroll
      for (int j = 0; j < 4; j++)
        Pt[(tx * 4 + j) * PT_STR + ty * 8 + i] = p[i][j];
    __syncthreads();

    // O += P * V  (128x128), thread: rows ty*8.., cols tx*8..
#pragma unroll 4
    for (int n = 0; n < BKV; n++) {
      float4 p0 = *(const float4*)&Pt[n * PT_STR + ty * 8];
      float4 p1 = *(const float4*)&Pt[n * PT_STR + ty * 8 + 4];
      float4 v0 = *(const float4*)&Vs[n * V_STR + tx * 8];
      float4 v1 = *(const float4*)&Vs[n * V_STR + tx * 8 + 4];
      float pv[8] = {p0.x, p0.y, p0.z, p0.w, p1.x, p1.y, p1.z, p1.w};
      float vv[8] = {v0.x, v0.y, v0.z, v0.w, v1.x, v1.y, v1.z, v1.w};
#pragma unroll
      for (int i = 0; i < 8; i++)
#pragma unroll
        for (int j = 0; j < 8; j++) acc[i][j] = fmaf(pv[i], vv[j], acc[i][j]);
    }
  }

  // epilogue: normalize and store
#pragma unroll
  for (int i = 0; i < 8; i++) {
    const float inv = 1.0f / l_i[i];
    float* Op = O + (size_t)(q0 + ty * 8 + i) * DM + h * HD + tx * 8;
    float4 o0 = {acc[i][0] * inv, acc[i][1] * inv, acc[i][2] * inv, acc[i][3] * inv};
    float4 o1 = {acc[i][4] * inv, acc[i][5] * inv, acc[i][6] * inv, acc[i][7] * inv};
    *(float4*)Op = o0;
    *(float4*)(Op + 4) = o1;
  }
}

// ---------------- launch ----------------------------------------------------
extern "C" void kernel_launch(void* const* d_in, const int* in_sizes, int n_in,
                              void* d_out, int out_size) {
  const float* x  = (const float*)d_in[0];
  const float* wq = (const float*)d_in[1];
  const float* wk = (const float*)d_in[2];
  const float* wv = (const float*)d_in[3];
  const float* wo = (const float*)d_in[4];
  float* out = (float*)d_out;

  float *q_p, *k_p, *v_p, *a_p;
  cudaGetSymbolAddress((void**)&q_p, g_q);
  cudaGetSymbolAddress((void**)&k_p, g_k);
  cudaGetSymbolAddress((void**)&v_p, g_v);
  cudaGetSymbolAddress((void**)&a_p, g_attn);

  // QKV projections
  sgemm_kernel<<<dim3(DM / 128, S_LEN / 128), 256>>>(x, wq, q_p, S_LEN, DM, DM);
  sgemm_kernel<<<dim3((NKV * HD) / 128, S_LEN / 128), 256>>>(x, wk, k_p, S_LEN, NKV * HD, DM);
  sgemm_kernel<<<dim3((NKV * HD) / 128, S_LEN / 128), 256>>>(x, wv, v_p, S_LEN, NKV * HD, DM);

  // RoPE on q and k
  rope_kernel<<<dim3(S_LEN, NH + NKV), 64>>>(q_p, k_p);

  // causal flash attention
  cudaFuncSetAttribute(flash_kernel, cudaFuncAttributeMaxDynamicSharedMemorySize,
                       FLASH_SMEM);
  flash_kernel<<<dim3(S_LEN / BQ, NH), 256, FLASH_SMEM>>>(q_p, k_p, v_p, a_p);

  // output projection
  sgemm_kernel<<<dim3(DM / 128, S_LEN / 128), 256>>>(a_p, wo, out, S_LEN, DM, DM);
}

// round 2
// speedup vs baseline: 1.6019x; 1.6019x over previous
#include <cuda_runtime.h>
#include <math.h>
#include <stdint.h>

#define S_LEN  4096
#define DM     2048
#define NH     16
#define NKV    4
#define HD     128

// ---------------- scratch (device globals; no runtime alloc allowed) --------
__device__ float g_q[(size_t)S_LEN * DM];          // 32 MB  [s][h*128+d]
__device__ float g_k[(size_t)S_LEN * NKV * HD];    // 8 MB   [s][kvh*128+d]
__device__ float g_v[(size_t)S_LEN * NKV * HD];    // 8 MB
__device__ float g_attn[(size_t)S_LEN * DM];       // 32 MB  [s][h*128+d]

// ---------------- tf32 helpers ---------------------------------------------
__device__ __forceinline__ uint32_t f2tf32(float x) {
  uint32_t u;
  asm("cvt.rna.tf32.f32 %0, %1;" : "=r"(u) : "f"(x));
  return u;
}

__device__ __forceinline__ void mma_tf32(float* c, const uint32_t* a,
                                         const uint32_t* b) {
  asm volatile(
      "mma.sync.aligned.m16n8k8.row.col.f32.tf32.tf32.f32 "
      "{%0,%1,%2,%3}, {%4,%5,%6,%7}, {%8,%9}, {%0,%1,%2,%3};"
      : "+f"(c[0]), "+f"(c[1]), "+f"(c[2]), "+f"(c[3])
      : "r"(a[0]), "r"(a[1]), "r"(a[2]), "r"(a[3]), "r"(b[0]), "r"(b[1]));
}

// ---------------- tf32 tensor-core GEMM: C = A[M,K] * B[K,N] ----------------
// 128x128 tile, BK=32, 256 threads (8 warps 2x4), warp does 64x32 via m16n8k8.
// Smem holds pre-swizzled fragment layouts:
//   A: [kstep(4)][mtile(8)][slot(32)] x uint4  — frag load = 1 LDS.128/lane
//   B: [kstep(4)][ntile(16)][slot(32)] x uint2 — frag load = 1 LDS.64/lane
__global__ __launch_bounds__(256) void gemm_tf32_kernel(
    const float* __restrict__ A, const float* __restrict__ B,
    float* __restrict__ C, int M, int N, int K) {
  __shared__ uint32_t smA[4 * 8 * 32 * 4];    // 16 KB
  __shared__ uint32_t smB[4 * 16 * 32 * 2];   // 16 KB

  const int tid = threadIdx.x;
  const int l = tid & 31;
  const int w = tid >> 5;
  const int bm = blockIdx.y * 128;
  const int bn = blockIdx.x * 128;
  const int warp_m = w >> 2;   // 0..1
  const int warp_n = w & 3;    // 0..3

  // ---- loader-side constants ----
  // A: iter i handles u = w + 8i; m = (u&3)*2 + (u>>2)*16 + l4*8 + l3
  const int l3 = (l >> 3) & 1;
  const int l4 = (l >> 4) & 1;
  int amrow[4];
#pragma unroll
  for (int i = 0; i < 4; i++) {
    int u = w + 8 * i;
    amrow[i] = (u & 3) * 2 + (u >> 2) * 16 + l4 * 8 + l3;
  }
  const int akcol = 8 * ((l >> 1) & 3) + 4 * (l & 1);  // k offset within BK
  // B: iter i handles global k row (w + 8i), n0 = 4*l
  const int bn0 = 4 * l;

  float acc[4][4][4];
#pragma unroll
  for (int mt = 0; mt < 4; mt++)
#pragma unroll
    for (int nt = 0; nt < 4; nt++)
#pragma unroll
      for (int c = 0; c < 4; c++) acc[mt][nt][c] = 0.0f;

  const int niter = K / 32;
  float4 aR[4], bR[4];

  // prologue: load tile 0 into regs
#pragma unroll
  for (int i = 0; i < 4; i++) {
    aR[i] = *(const float4*)(A + (size_t)(bm + amrow[i]) * K + akcol);
    bR[i] = *(const float4*)(B + (size_t)(w + 8 * i) * N + bn + bn0);
  }

  for (int kt = 0; kt < niter; kt++) {
    __syncthreads();
    // ---- STS current tile (convert to tf32, pre-swizzled fragment layout) --
    {
      const int kstepA = (l >> 1) & 3;
      const int t2A = l & 1;
#pragma unroll
      for (int i = 0; i < 4; i++) {
        const int m = amrow[i];
        const int mtile = m >> 4;
        const int r = m & 7;
        const int c = ((m >> 3) & 1) + 2 * t2A;
        const int base = ((kstepA * 8 + mtile) * 32) * 4 + c;
        const float v[4] = {aR[i].x, aR[i].y, aR[i].z, aR[i].w};
#pragma unroll
        for (int q = 0; q < 4; q++) {
          const int slot = ((r << 2) | q) ^ kstepA;
          smA[base + slot * 4] = f2tf32(v[q]);
        }
      }
#pragma unroll
      for (int i = 0; i < 4; i++) {
        const int k_in = w + 8 * i;
        const int kstep = k_in >> 3;
        const int kj = k_in & 3;
        const int t2 = (k_in >> 2) & 1;
        const float v[4] = {bR[i].x, bR[i].y, bR[i].z, bR[i].w};
#pragma unroll
        for (int q = 0; q < 4; q++) {
          const int n_g = bn0 + q;
          const int ntile = n_g >> 3;
          const int n_in = n_g & 7;
          const int slot = ((n_in << 2) | kj) ^ ntile;
          smB[((kstep * 16 + ntile) * 32 + slot) * 2 + t2] = f2tf32(v[q]);
        }
      }
    }
    __syncthreads();

    // ---- prefetch next tile into regs ----
    if (kt + 1 < niter) {
      const int kb = (kt + 1) * 32;
#pragma unroll
      for (int i = 0; i < 4; i++) {
        aR[i] = *(const float4*)(A + (size_t)(bm + amrow[i]) * K + kb + akcol);
        bR[i] = *(const float4*)(B + (size_t)(kb + w + 8 * i) * N + bn + bn0);
      }
    }

    // ---- compute: 4 k8-steps x 16 mma ----
#pragma unroll
    for (int ks = 0; ks < 4; ks++) {
      uint4 af[4];
      uint2 bf[4];
#pragma unroll
      for (int mt = 0; mt < 4; mt++) {
        const int mtile = warp_m * 4 + mt;
        af[mt] = ((const uint4*)smA)[(ks * 8 + mtile) * 32 + (l ^ ks)];
      }
#pragma unroll
      for (int nt = 0; nt < 4; nt++) {
        const int ntile = warp_n * 4 + nt;
        bf[nt] = ((const uint2*)smB)[(ks * 16 + ntile) * 32 + (l ^ ntile)];
      }
#pragma unroll
      for (int mt = 0; mt < 4; mt++) {
        const uint32_t a[4] = {af[mt].x, af[mt].y, af[mt].z, af[mt].w};
#pragma unroll
        for (int nt = 0; nt < 4; nt++) {
          const uint32_t b[2] = {bf[nt].x, bf[nt].y};
          mma_tf32(acc[mt][nt], a, b);
        }
      }
    }
  }

  // ---- epilogue ----
#pragma unroll
  for (int mt = 0; mt < 4; mt++) {
    const int row = bm + warp_m * 64 + mt * 16 + (l >> 2);
#pragma unroll
    for (int nt = 0; nt < 4; nt++) {
      const int col = bn + warp_n * 32 + nt * 8 + 2 * (l & 3);
      float2 lo = {acc[mt][nt][0], acc[mt][nt][1]};
      float2 hi = {acc[mt][nt][2], acc[mt][nt][3]};
      *(float2*)(C + (size_t)row * N + col) = lo;
      *(float2*)(C + (size_t)(row + 8) * N + col) = hi;
    }
  }
}

// ---------------- RoPE -----------------------------------------------------
__global__ void rope_kernel(float* __restrict__ q, float* __restrict__ k) {
  const int s = blockIdx.x;
  const int hh = blockIdx.y;
  const int d = threadIdx.x;   // 0..63
  float* ptr;
  if (hh < NH) ptr = q + (size_t)s * DM + hh * HD;
  else         ptr = k + (size_t)s * (NKV * HD) + (hh - NH) * HD;
  float inv = powf(10000.0f, -((float)(2 * d) / 128.0f));
  float ang = (float)s * inv;
  float sn, c;
  sincosf(ang, &sn, &c);
  float x0 = ptr[d];
  float x1 = ptr[d + 64];
  ptr[d]      = x0 * c - x1 * sn;
  ptr[d + 64] = x1 * c + x0 * sn;
}

// ---------------- Flash attention (causal, GQA) -----------------------------
#define BQ 128
#define BKV 64
#define QT_STR (BQ + 4)   // 132
#define KT_STR (BKV + 4)  // 68
#define V_STR  (HD + 4)   // 132
#define PT_STR (BQ + 4)   // 132
#define FLASH_SMEM ((HD * QT_STR + HD * KT_STR + BKV * V_STR + BKV * PT_STR) * 4)

__global__ __launch_bounds__(256, 1) void flash_kernel(
    const float* __restrict__ Q, const float* __restrict__ K,
    const float* __restrict__ V, float* __restrict__ O) {
  extern __shared__ float smem[];
  float* Qt = smem;                       // [HD][QT_STR]
  float* Kt = Qt + HD * QT_STR;           // [HD][KT_STR]
  float* Vs = Kt + HD * KT_STR;           // [BKV][V_STR]
  float* Pt = Vs + BKV * V_STR;           // [BKV][PT_STR]

  const int h  = blockIdx.y;
  const int qb = gridDim.x - 1 - blockIdx.x;
  const int q0 = qb * BQ;
  const int kvh = h >> 2;
  const int tid = threadIdx.x;
  const int tx = tid & 15, ty = tid >> 4;

  for (int f = tid; f < BQ * (HD / 4); f += 256) {
    int m = f >> 5;
    int d4 = (f & 31) * 4;
    float4 v = *(const float4*)(Q + (size_t)(q0 + m) * DM + h * HD + d4);
    Qt[(d4 + 0) * QT_STR + m] = v.x;
    Qt[(d4 + 1) * QT_STR + m] = v.y;
    Qt[(d4 + 2) * QT_STR + m] = v.z;
    Qt[(d4 + 3) * QT_STR + m] = v.w;
  }

  float acc[8][8];
  float m_i[8], l_i[8];
#pragma unroll
  for (int i = 0; i < 8; i++) {
    m_i[i] = -3.0e38f;
    l_i[i] = 0.0f;
#pragma unroll
    for (int j = 0; j < 8; j++) acc[i][j] = 0.0f;
  }

  const int ntiles = (q0 + BQ) / BKV;
  const float scale = 0.08838834764831845f;

  for (int t = 0; t < ntiles; t++) {
    __syncthreads();
    for (int f = tid; f < BKV * (HD / 4); f += 256) {
      int n = f >> 5;
      int d4 = (f & 31) * 4;
      float4 v = *(const float4*)(K + (size_t)(t * BKV + n) * (NKV * HD) + kvh * HD + d4);
      Kt[(d4 + 0) * KT_STR + n] = v.x;
      Kt[(d4 + 1) * KT_STR + n] = v.y;
      Kt[(d4 + 2) * KT_STR + n] = v.z;
      Kt[(d4 + 3) * KT_STR + n] = v.w;
    }
    for (int f = tid; f < BKV * (HD / 4); f += 256) {
      int n = f >> 5;
      int d4 = (f & 31) * 4;
      *(float4*)&Vs[n * V_STR + d4] =
          *(const float4*)(V + (size_t)(t * BKV + n) * (NKV * HD) + kvh * HD + d4);
    }
    __syncthreads();

    float s[8][4];
#pragma unroll
    for (int i = 0; i < 8; i++)
#pragma unroll
      for (int j = 0; j < 4; j++) s[i][j] = 0.0f;
#pragma unroll 8
    for (int kk = 0; kk < HD; kk++) {
      float4 a0 = *(const float4*)&Qt[kk * QT_STR + ty * 8];
      float4 a1 = *(const float4*)&Qt[kk * QT_STR + ty * 8 + 4];
      float4 b  = *(const float4*)&Kt[kk * KT_STR + tx * 4];
      float av[8] = {a0.x, a0.y, a0.z, a0.w, a1.x, a1.y, a1.z, a1.w};
      float bv[4] = {b.x, b.y, b.z, b.w};
#pragma unroll
      for (int i = 0; i < 8; i++)
#pragma unroll
        for (int j = 0; j < 4; j++) s[i][j] = fmaf(av[i], bv[j], s[i][j]);
    }

    float p[8][4];
    float alpha[8];
#pragma unroll
    for (int i = 0; i < 8; i++) {
      const int qr = q0 + ty * 8 + i;
      float mx = -3.0e38f;
#pragma unroll
      for (int j = 0; j < 4; j++) {
        float sv = (t * BKV + tx * 4 + j <= qr) ? s[i][j] * scale : -3.0e38f;
        s[i][j] = sv;
        mx = fmaxf(mx, sv);
      }
#pragma unroll
      for (int o = 8; o >= 1; o >>= 1)
        mx = fmaxf(mx, __shfl_xor_sync(0xffffffffu, mx, o));
      const float mn = fmaxf(m_i[i], mx);
      float rs = 0.0f;
#pragma unroll
      for (int j = 0; j < 4; j++) {
        float pv = __expf(s[i][j] - mn);
        p[i][j] = pv;
        rs += pv;
      }
#pragma unroll
      for (int o = 8; o >= 1; o >>= 1)
        rs += __shfl_xor_sync(0xffffffffu, rs, o);
      alpha[i] = __expf(m_i[i] - mn);
      l_i[i] = l_i[i] * alpha[i] + rs;
      m_i[i] = mn;
    }
#pragma unroll
    for (int i = 0; i < 8; i++)
#pragma unroll
      for (int j = 0; j < 8; j++) acc[i][j] *= alpha[i];

#pragma unroll
    for (int i = 0; i < 8; i++)
#pragma unroll
      for (int j = 0; j < 4; j++)
        Pt[(tx * 4 + j) * PT_STR + ty * 8 + i] = p[i][j];
    __syncthreads();

#pragma unroll 4
    for (int n = 0; n < BKV; n++) {
      float4 p0 = *(const float4*)&Pt[n * PT_STR + ty * 8];
      float4 p1 = *(const float4*)&Pt[n * PT_STR + ty * 8 + 4];
      float4 v0 = *(const float4*)&Vs[n * V_STR + tx * 8];
      float4 v1 = *(const float4*)&Vs[n * V_STR + tx * 8 + 4];
      float pv[8] = {p0.x, p0.y, p0.z, p0.w, p1.x, p1.y, p1.z, p1.w};
      float vv[8] = {v0.x, v0.y, v0.z, v0.w, v1.x, v1.y, v1.z, v1.w};
#pragma unroll
      for (int i = 0; i < 8; i++)
#pragma unroll
        for (int j = 0; j < 8; j++) acc[i][j] = fmaf(pv[i], vv[j], acc[i][j]);
    }
  }

#pragma unroll
  for (int i = 0; i < 8; i++) {
    const float inv = 1.0f / l_i[i];
    float* Op = O + (size_t)(q0 + ty * 8 + i) * DM + h * HD + tx * 8;
    float4 o0 = {acc[i][0] * inv, acc[i][1] * inv, acc[i][2] * inv, acc[i][3] * inv};
    float4 o1 = {acc[i][4] * inv, acc[i][5] * inv, acc[i][6] * inv, acc[i][7] * inv};
    *(float4*)Op = o0;
    *(float4*)(Op + 4) = o1;
  }
}

// ---------------- launch ----------------------------------------------------
extern "C" void kernel_launch(void* const* d_in, const int* in_sizes, int n_in,
                              void* d_out, int out_size) {
  const float* x  = (const float*)d_in[0];
  const float* wq = (const float*)d_in[1];
  const float* wk = (const float*)d_in[2];
  const float* wv = (const float*)d_in[3];
  const float* wo = (const float*)d_in[4];
  float* out = (float*)d_out;

  float *q_p, *k_p, *v_p, *a_p;
  cudaGetSymbolAddress((void**)&q_p, g_q);
  cudaGetSymbolAddress((void**)&k_p, g_k);
  cudaGetSymbolAddress((void**)&v_p, g_v);
  cudaGetSymbolAddress((void**)&a_p, g_attn);

  // QKV projections (tf32 tensor cores)
  gemm_tf32_kernel<<<dim3(DM / 128, S_LEN / 128), 256>>>(x, wq, q_p, S_LEN, DM, DM);
  gemm_tf32_kernel<<<dim3((NKV * HD) / 128, S_LEN / 128), 256>>>(x, wk, k_p, S_LEN, NKV * HD, DM);
  gemm_tf32_kernel<<<dim3((NKV * HD) / 128, S_LEN / 128), 256>>>(x, wv, v_p, S_LEN, NKV * HD, DM);

  // RoPE on q and k
  rope_kernel<<<dim3(S_LEN, NH + NKV), 64>>>(q_p, k_p);

  // causal flash attention (fp32 SIMT)
  cudaFuncSetAttribute(flash_kernel, cudaFuncAttributeMaxDynamicSharedMemorySize,
                       FLASH_SMEM);
  flash_kernel<<<dim3(S_LEN / BQ, NH), 256, FLASH_SMEM>>>(q_p, k_p, v_p, a_p);

  // output projection (tf32 tensor cores)
  gemm_tf32_kernel<<<dim3(DM / 128, S_LEN / 128), 256>>>(a_p, wo, out, S_LEN, DM, DM);
}

// round 3
// speedup vs baseline: 3.2749x; 2.0444x over previous
#include <cuda_runtime.h>
#include <math.h>
#include <stdint.h>

#define S_LEN  4096
#define DM     2048
#define NH     16
#define NKV    4
#define HD     128

// ---------------- scratch (device globals; no runtime alloc allowed) --------
__device__ float g_q[(size_t)S_LEN * DM];          // 32 MB  [s][h*128+d]
__device__ float g_k[(size_t)S_LEN * NKV * HD];    // 8 MB   [s][kvh*128+d]
__device__ float g_v[(size_t)S_LEN * NKV * HD];    // 8 MB
__device__ float g_attn[(size_t)S_LEN * DM];       // 32 MB  [s][h*128+d]

// ---------------- tf32 helpers ---------------------------------------------
__device__ __forceinline__ uint32_t f2tf32(float x) {
  uint32_t u;
  asm("cvt.rna.tf32.f32 %0, %1;" : "=r"(u) : "f"(x));
  return u;
}

__device__ __forceinline__ void mma_tf32(float* c, const uint32_t* a,
                                         const uint32_t* b) {
  asm volatile(
      "mma.sync.aligned.m16n8k8.row.col.f32.tf32.tf32.f32 "
      "{%0,%1,%2,%3}, {%4,%5,%6,%7}, {%8,%9}, {%0,%1,%2,%3};"
      : "+f"(c[0]), "+f"(c[1]), "+f"(c[2]), "+f"(c[3])
      : "r"(a[0]), "r"(a[1]), "r"(a[2]), "r"(a[3]), "r"(b[0]), "r"(b[1]));
}

// ---------------- tf32 tensor-core GEMM: C = A[M,K] * B[K,N] ----------------
// (unchanged from round 2 — verified correct)
__global__ __launch_bounds__(256) void gemm_tf32_kernel(
    const float* __restrict__ A, const float* __restrict__ B,
    float* __restrict__ C, int M, int N, int K) {
  __shared__ uint32_t smA[4 * 8 * 32 * 4];    // 16 KB
  __shared__ uint32_t smB[4 * 16 * 32 * 2];   // 16 KB

  const int tid = threadIdx.x;
  const int l = tid & 31;
  const int w = tid >> 5;
  const int bm = blockIdx.y * 128;
  const int bn = blockIdx.x * 128;
  const int warp_m = w >> 2;
  const int warp_n = w & 3;

  const int l3 = (l >> 3) & 1;
  const int l4 = (l >> 4) & 1;
  int amrow[4];
#pragma unroll
  for (int i = 0; i < 4; i++) {
    int u = w + 8 * i;
    amrow[i] = (u & 3) * 2 + (u >> 2) * 16 + l4 * 8 + l3;
  }
  const int akcol = 8 * ((l >> 1) & 3) + 4 * (l & 1);
  const int bn0 = 4 * l;

  float acc[4][4][4];
#pragma unroll
  for (int mt = 0; mt < 4; mt++)
#pragma unroll
    for (int nt = 0; nt < 4; nt++)
#pragma unroll
      for (int c = 0; c < 4; c++) acc[mt][nt][c] = 0.0f;

  const int niter = K / 32;
  float4 aR[4], bR[4];

#pragma unroll
  for (int i = 0; i < 4; i++) {
    aR[i] = *(const float4*)(A + (size_t)(bm + amrow[i]) * K + akcol);
    bR[i] = *(const float4*)(B + (size_t)(w + 8 * i) * N + bn + bn0);
  }

  for (int kt = 0; kt < niter; kt++) {
    __syncthreads();
    {
      const int kstepA = (l >> 1) & 3;
      const int t2A = l & 1;
#pragma unroll
      for (int i = 0; i < 4; i++) {
        const int m = amrow[i];
        const int mtile = m >> 4;
        const int r = m & 7;
        const int c = ((m >> 3) & 1) + 2 * t2A;
        const int base = ((kstepA * 8 + mtile) * 32) * 4 + c;
        const float v[4] = {aR[i].x, aR[i].y, aR[i].z, aR[i].w};
#pragma unroll
        for (int q = 0; q < 4; q++) {
          const int slot = ((r << 2) | q) ^ kstepA;
          smA[base + slot * 4] = f2tf32(v[q]);
        }
      }
#pragma unroll
      for (int i = 0; i < 4; i++) {
        const int k_in = w + 8 * i;
        const int kstep = k_in >> 3;
        const int kj = k_in & 3;
        const int t2 = (k_in >> 2) & 1;
        const float v[4] = {bR[i].x, bR[i].y, bR[i].z, bR[i].w};
#pragma unroll
        for (int q = 0; q < 4; q++) {
          const int n_g = bn0 + q;
          const int ntile = n_g >> 3;
          const int n_in = n_g & 7;
          const int slot = ((n_in << 2) | kj) ^ ntile;
          smB[((kstep * 16 + ntile) * 32 + slot) * 2 + t2] = f2tf32(v[q]);
        }
      }
    }
    __syncthreads();

    if (kt + 1 < niter) {
      const int kb = (kt + 1) * 32;
#pragma unroll
      for (int i = 0; i < 4; i++) {
        aR[i] = *(const float4*)(A + (size_t)(bm + amrow[i]) * K + kb + akcol);
        bR[i] = *(const float4*)(B + (size_t)(kb + w + 8 * i) * N + bn + bn0);
      }
    }

#pragma unroll
    for (int ks = 0; ks < 4; ks++) {
      uint4 af[4];
      uint2 bf[4];
#pragma unroll
      for (int mt = 0; mt < 4; mt++) {
        const int mtile = warp_m * 4 + mt;
        af[mt] = ((const uint4*)smA)[(ks * 8 + mtile) * 32 + (l ^ ks)];
      }
#pragma unroll
      for (int nt = 0; nt < 4; nt++) {
        const int ntile = warp_n * 4 + nt;
        bf[nt] = ((const uint2*)smB)[(ks * 16 + ntile) * 32 + (l ^ ntile)];
      }
#pragma unroll
      for (int mt = 0; mt < 4; mt++) {
        const uint32_t a[4] = {af[mt].x, af[mt].y, af[mt].z, af[mt].w};
#pragma unroll
        for (int nt = 0; nt < 4; nt++) {
          const uint32_t b[2] = {bf[nt].x, bf[nt].y};
          mma_tf32(acc[mt][nt], a, b);
        }
      }
    }
  }

#pragma unroll
  for (int mt = 0; mt < 4; mt++) {
    const int row = bm + warp_m * 64 + mt * 16 + (l >> 2);
#pragma unroll
    for (int nt = 0; nt < 4; nt++) {
      const int col = bn + warp_n * 32 + nt * 8 + 2 * (l & 3);
      float2 lo = {acc[mt][nt][0], acc[mt][nt][1]};
      float2 hi = {acc[mt][nt][2], acc[mt][nt][3]};
      *(float2*)(C + (size_t)row * N + col) = lo;
      *(float2*)(C + (size_t)(row + 8) * N + col) = hi;
    }
  }
}

// ---------------- RoPE -----------------------------------------------------
__global__ void rope_kernel(float* __restrict__ q, float* __restrict__ k) {
  const int s = blockIdx.x;
  const int hh = blockIdx.y;
  const int d = threadIdx.x;   // 0..63
  float* ptr;
  if (hh < NH) ptr = q + (size_t)s * DM + hh * HD;
  else         ptr = k + (size_t)s * (NKV * HD) + (hh - NH) * HD;
  float inv = powf(10000.0f, -((float)(2 * d) / 128.0f));
  float ang = (float)s * inv;
  float sn, c;
  sincosf(ang, &sn, &c);
  float x0 = ptr[d];
  float x1 = ptr[d + 64];
  ptr[d]      = x0 * c - x1 * sn;
  ptr[d + 64] = x1 * c + x0 * sn;
}

// ---------------- Flash attention on tensor cores (tf32 mma) ----------------
// BQ=128 (8 warps x 16 rows), BKV=64, HD=128.
// Smem (in 32-bit words):
//   Qa: A-frag planes [ks16][mt8][pair2][half2][slot8 x uint4]  = 16384 w (64KB)
//   Kf: B-frag planes [ks16][nt8][pair2][slot8 x uint4]         =  8192 w (32KB)
//   Vf: B-frag planes [ks8][nt16] stride 68: pair*32+slot*4+kj  =  8704 w (34KB)
//   Ps: per-warp P scratch [w8][row16][68]                      =  8704 w (34KB)
#define BQ 128
#define BKV 64
#define F_SMEM_WORDS (16384 + 8192 + 8704 + 8704)
#define F_SMEM_BYTES (F_SMEM_WORDS * 4)

__global__ __launch_bounds__(256, 1) void flash_mma_kernel(
    const float* __restrict__ Q, const float* __restrict__ K,
    const float* __restrict__ V, float* __restrict__ Og) {
  extern __shared__ uint4 smem4[];
  uint32_t* Qw = (uint32_t*)smem4;            // 16384 words
  uint32_t* Kw = Qw + 16384;                  // 8192 words
  uint32_t* Vf = Kw + 8192;                   // 8704 words
  uint32_t* Ps = Vf + 8704;                   // 8704 words

  const int h  = blockIdx.y;
  const int qb = gridDim.x - 1 - blockIdx.x;  // long blocks first
  const int q0 = qb * BQ;
  const int kvh = h >> 2;
  const int tid = threadIdx.x;
  const int l = tid & 31;
  const int w = tid >> 5;

  const int lq = l >> 2;        // 0..7 (row group)
  const int lc = l & 3;         // 0..3 (col group)

  // ---- stage Q tile as A-fragments (tf32) ----
  // iter i: row = w + 8i; lane: ks = l>>1, pair = l&1, d0 = 4l
  {
    const int ks = l >> 1, pair = l & 1;
#pragma unroll
    for (int i = 0; i < 16; i++) {
      const int row = w + 8 * i;
      float4 qv = *(const float4*)(Q + (size_t)(q0 + row) * DM + h * HD + 4 * l);
      const int mt = row >> 4, half = (row >> 3) & 1;
      const int slot = (row & 7) ^ (ks & 7);
      uint4 u = {f2tf32(qv.x), f2tf32(qv.y), f2tf32(qv.z), f2tf32(qv.w)};
      smem4[(((ks * 8 + mt) * 2 + pair) * 2 + half) * 8 + slot] = u;
    }
  }

  float m_i0 = -3.0e38f, m_i1 = -3.0e38f;
  float l_i0 = 0.0f, l_i1 = 0.0f;
  float O[16][4];
#pragma unroll
  for (int nt = 0; nt < 16; nt++)
#pragma unroll
    for (int c = 0; c < 4; c++) O[nt][c] = 0.0f;

  __syncthreads();

  const int ntiles = (q0 + BQ) / BKV;
  const float scale = 0.08838834764831845f;
  const int psbase = w * 1088;  // 16*68

  for (int t = 0; t < ntiles; t++) {
    __syncthreads();
    // ---- stage K tile (B-frags) ----
    {
      const int ks = l >> 1, pair = l & 1;
#pragma unroll
      for (int i = 0; i < 8; i++) {
        const int row = w + 8 * i;  // kv in tile
        float4 kv4 = *(const float4*)(K + (size_t)(t * BKV + row) * (NKV * HD) +
                                      kvh * HD + 4 * l);
        const int nt = row >> 3;
        const int slot = (row & 7) ^ (ks & 7);
        uint4 u = {f2tf32(kv4.x), f2tf32(kv4.y), f2tf32(kv4.z), f2tf32(kv4.w)};
        ((uint4*)Kw)[((ks * 8 + nt) * 2 + pair) * 8 + slot] = u;
      }
    }
    // ---- stage V tile (B-frags, transpose scatter) ----
    {
      const int ntv = l >> 1;
      const int nbase = 4 * (l & 1);
#pragma unroll
      for (int i = 0; i < 8; i++) {
        const int row = w + 8 * i;  // kv = k index
        float4 vv = *(const float4*)(V + (size_t)(t * BKV + row) * (NKV * HD) +
                                     kvh * HD + 4 * l);
        const int ksv = row >> 3, pair = (row >> 2) & 1, kj = row & 3;
        uint32_t* base = Vf + (ksv * 16 + ntv) * 68 + pair * 32 + kj;
        base[(nbase + 0) * 4] = f2tf32(vv.x);
        base[(nbase + 1) * 4] = f2tf32(vv.y);
        base[(nbase + 2) * 4] = f2tf32(vv.z);
        base[(nbase + 3) * 4] = f2tf32(vv.w);
      }
    }
    __syncthreads();

    const bool active = (t * BKV <= q0 + 16 * w + 15);
    if (active) {
      // ---- S = Q K^T (128x64 per CTA, 16x64 per warp) ----
      float S[8][4];
#pragma unroll
      for (int nt = 0; nt < 8; nt++)
#pragma unroll
        for (int c = 0; c < 4; c++) S[nt][c] = 0.0f;

#pragma unroll
      for (int ks = 0; ks < 16; ks++) {
        const int sl = lq ^ (ks & 7);
        const int qbas = ((ks * 8 + w) * 32 + sl) * 4 + lc;
        uint32_t a[4];
        a[0] = Qw[qbas];
        a[1] = Qw[qbas + 32];   // half=1
        a[2] = Qw[qbas + 64];   // pair=1
        a[3] = Qw[qbas + 96];
#pragma unroll
        for (int nt = 0; nt < 8; nt++) {
          const int kbas = ((ks * 8 + nt) * 16 + sl) * 4 + lc;
          uint32_t b[2];
          b[0] = Kw[kbas];
          b[1] = Kw[kbas + 32];  // pair=1
          mma_tf32(S[nt], a, b);
        }
      }

      // ---- scale + causal mask ----
#pragma unroll
      for (int nt = 0; nt < 8; nt++)
#pragma unroll
        for (int c = 0; c < 4; c++) S[nt][c] *= scale;

      const int rowg0 = q0 + 16 * w + lq;
      const int rowg1 = rowg0 + 8;
      if (t * BKV + BKV - 1 > q0 + 16 * w) {
#pragma unroll
        for (int nt = 0; nt < 8; nt++) {
          const int c0 = t * BKV + nt * 8 + 2 * lc;
          if (c0 > rowg0)     S[nt][0] = -3.0e38f;
          if (c0 + 1 > rowg0) S[nt][1] = -3.0e38f;
          if (c0 > rowg1)     S[nt][2] = -3.0e38f;
          if (c0 + 1 > rowg1) S[nt][3] = -3.0e38f;
        }
      }

      // ---- online softmax ----
      float mx0 = -3.0e38f, mx1 = -3.0e38f;
#pragma unroll
      for (int nt = 0; nt < 8; nt++) {
        mx0 = fmaxf(mx0, fmaxf(S[nt][0], S[nt][1]));
        mx1 = fmaxf(mx1, fmaxf(S[nt][2], S[nt][3]));
      }
      mx0 = fmaxf(mx0, __shfl_xor_sync(0xffffffffu, mx0, 1));
      mx0 = fmaxf(mx0, __shfl_xor_sync(0xffffffffu, mx0, 2));
      mx1 = fmaxf(mx1, __shfl_xor_sync(0xffffffffu, mx1, 1));
      mx1 = fmaxf(mx1, __shfl_xor_sync(0xffffffffu, mx1, 2));
      const float mn0 = fmaxf(m_i0, mx0);
      const float mn1 = fmaxf(m_i1, mx1);

      float rs0 = 0.0f, rs1 = 0.0f;
      const int ps0 = psbase + lq * 68 + 2 * lc;
      const int ps1 = psbase + (lq + 8) * 68 + 2 * lc;
#pragma unroll
      for (int nt = 0; nt < 8; nt++) {
        float p0 = __expf(S[nt][0] - mn0);
        float p1 = __expf(S[nt][1] - mn0);
        float p2 = __expf(S[nt][2] - mn1);
        float p3 = __expf(S[nt][3] - mn1);
        rs0 += p0 + p1;
        rs1 += p2 + p3;
        Ps[ps0 + nt * 8]     = f2tf32(p0);
        Ps[ps0 + nt * 8 + 1] = f2tf32(p1);
        Ps[ps1 + nt * 8]     = f2tf32(p2);
        Ps[ps1 + nt * 8 + 1] = f2tf32(p3);
      }
      rs0 += __shfl_xor_sync(0xffffffffu, rs0, 1);
      rs0 += __shfl_xor_sync(0xffffffffu, rs0, 2);
      rs1 += __shfl_xor_sync(0xffffffffu, rs1, 1);
      rs1 += __shfl_xor_sync(0xffffffffu, rs1, 2);
      const float alpha0 = __expf(m_i0 - mn0);
      const float alpha1 = __expf(m_i1 - mn1);
      l_i0 = l_i0 * alpha0 + rs0;
      l_i1 = l_i1 * alpha1 + rs1;
      m_i0 = mn0;
      m_i1 = mn1;
#pragma unroll
      for (int nt = 0; nt < 16; nt++) {
        O[nt][0] *= alpha0;
        O[nt][1] *= alpha0;
        O[nt][2] *= alpha1;
        O[nt][3] *= alpha1;
      }
      __syncwarp();

      // ---- O += P V  (16x128 per warp) ----
#pragma unroll
      for (int ks = 0; ks < 8; ks++) {
        uint32_t a[4];
        const int pa0 = psbase + lq * 68 + ks * 8 + lc;
        a[0] = Ps[pa0];
        a[1] = Ps[pa0 + 544];   // row +8
        a[2] = Ps[pa0 + 4];     // col +4
        a[3] = Ps[pa0 + 548];
#pragma unroll
        for (int nt = 0; nt < 16; nt++) {
          const int vb = (ks * 16 + nt) * 68 + lq * 4 + lc;
          uint32_t b[2];
          b[0] = Vf[vb];
          b[1] = Vf[vb + 32];  // pair=1
          mma_tf32(O[nt], a, b);
        }
      }
      __syncwarp();
    }
  }

  // ---- epilogue: normalize + store ----
  const float inv0 = 1.0f / l_i0;
  const float inv1 = 1.0f / l_i1;
  const int row0 = q0 + 16 * w + lq;
#pragma unroll
  for (int nt = 0; nt < 16; nt++) {
    const int col = h * HD + nt * 8 + 2 * lc;
    float2 v0 = {O[nt][0] * inv0, O[nt][1] * inv0};
    float2 v1 = {O[nt][2] * inv1, O[nt][3] * inv1};
    *(float2*)(Og + (size_t)row0 * DM + col) = v0;
    *(float2*)(Og + (size_t)(row0 + 8) * DM + col) = v1;
  }
}

// ---------------- launch ----------------------------------------------------
extern "C" void kernel_launch(void* const* d_in, const int* in_sizes, int n_in,
                              void* d_out, int out_size) {
  const float* x  = (const float*)d_in[0];
  const float* wq = (const float*)d_in[1];
  const float* wk = (const float*)d_in[2];
  const float* wv = (const float*)d_in[3];
  const float* wo = (const float*)d_in[4];
  float* out = (float*)d_out;

  float *q_p, *k_p, *v_p, *a_p;
  cudaGetSymbolAddress((void**)&q_p, g_q);
  cudaGetSymbolAddress((void**)&k_p, g_k);
  cudaGetSymbolAddress((void**)&v_p, g_v);
  cudaGetSymbolAddress((void**)&a_p, g_attn);

  // QKV projections (tf32 tensor cores)
  gemm_tf32_kernel<<<dim3(DM / 128, S_LEN / 128), 256>>>(x, wq, q_p, S_LEN, DM, DM);
  gemm_tf32_kernel<<<dim3((NKV * HD) / 128, S_LEN / 128), 256>>>(x, wk, k_p, S_LEN, NKV * HD, DM);
  gemm_tf32_kernel<<<dim3((NKV * HD) / 128, S_LEN / 128), 256>>>(x, wv, v_p, S_LEN, NKV * HD, DM);

  // RoPE on q and k
  rope_kernel<<<dim3(S_LEN, NH + NKV), 64>>>(q_p, k_p);

  // causal flash attention (tf32 tensor cores)
  cudaFuncSetAttribute(flash_mma_kernel,
                       cudaFuncAttributeMaxDynamicSharedMemorySize, F_SMEM_BYTES);
  flash_mma_kernel<<<dim3(S_LEN / BQ, NH), 256, F_SMEM_BYTES>>>(q_p, k_p, v_p, a_p);

  // output projection (tf32 tensor cores)
  gemm_tf32_kernel<<<dim3(DM / 128, S_LEN / 128), 256>>>(a_p, wo, out, S_LEN, DM, DM);
}

// round 4
// speedup vs baseline: 3.4757x; 1.0613x over previous
#include <cuda_runtime.h>
#include <math.h>
#include <stdint.h>

#define S_LEN  4096
#define DM     2048
#define NH     16
#define NKV    4
#define HD     128

// ---------------- scratch (device globals; no runtime alloc allowed) --------
__device__ float g_q[(size_t)S_LEN * DM];          // 32 MB  [s][h*128+d]
__device__ float g_k[(size_t)S_LEN * NKV * HD];    // 8 MB
__device__ float g_v[(size_t)S_LEN * NKV * HD];    // 8 MB
__device__ float g_attn[(size_t)S_LEN * DM];       // 32 MB

// packed tf32 fragment-layout operands
__device__ uint32_t g_px[(size_t)S_LEN * DM];        // x      (A-layout)
__device__ uint32_t g_pattn[(size_t)S_LEN * DM];     // attn   (A-layout)
__device__ uint32_t g_pwq[(size_t)DM * DM];          // wq     (B-layout)
__device__ uint32_t g_pwk[(size_t)DM * NKV * HD];    // wk
__device__ uint32_t g_pwv[(size_t)DM * NKV * HD];    // wv
__device__ uint32_t g_pwo[(size_t)DM * DM];          // wo

// ---------------- tf32 helpers ---------------------------------------------
__device__ __forceinline__ uint32_t f2tf32(float x) {
  uint32_t u;
  asm("cvt.rna.tf32.f32 %0, %1;" : "=r"(u) : "f"(x));
  return u;
}

__device__ __forceinline__ void mma_tf32(float* c, const uint32_t* a,
                                         const uint32_t* b) {
  asm volatile(
      "mma.sync.aligned.m16n8k8.row.col.f32.tf32.tf32.f32 "
      "{%0,%1,%2,%3}, {%4,%5,%6,%7}, {%8,%9}, {%0,%1,%2,%3};"
      : "+f"(c[0]), "+f"(c[1]), "+f"(c[2]), "+f"(c[3])
      : "r"(a[0]), "r"(a[1]), "r"(a[2]), "r"(a[3]), "r"(b[0]), "r"(b[1]));
}

__device__ __forceinline__ void cp16(uint32_t s, const void* g) {
  asm volatile("cp.async.cg.shared.global [%0], [%1], 16;" ::"r"(s), "l"(g));
}

// ---------------- pack kernels ---------------------------------------------
// A-layout tile (128 rows x 32 k): word = (ks*8+mtile)*128 + slot*4 + c
//   slot = ((r<<2)|q)^ks,  c = ((mloc>>3)&1) + 2*t2,  k = kt*32+8*ks+4*t2+q
__global__ __launch_bounds__(256) void pack_a_kernel(
    const float* __restrict__ A, uint32_t* __restrict__ P, int M, int K) {
  const int nq = K >> 2;
  const int idx = blockIdx.x * 256 + threadIdx.x;
  if (idx >= M * nq) return;
  const int m = idx / nq;
  const int k = (idx - m * nq) << 2;
  float4 v = *(const float4*)(A + (size_t)m * K + k);
  const int kt = k >> 5, koff = k & 31, ks = koff >> 3, t2 = (koff >> 2) & 1;
  const int mband = m >> 7, mloc = m & 127;
  const int mtile = mloc >> 4, r = mloc & 7, h3 = (mloc >> 3) & 1;
  const int c = h3 + 2 * t2;
  uint32_t* base =
      P + ((size_t)(mband * (K >> 5) + kt)) * 4096 + (ks * 8 + mtile) * 128 + c;
  const float vv[4] = {v.x, v.y, v.z, v.w};
#pragma unroll
  for (int q = 0; q < 4; q++) {
    const int slot = ((r << 2) | q) ^ ks;
    base[slot * 4] = f2tf32(vv[q]);
  }
}

// B-layout tile (32 k x 128 cols): word = ((ks*16+ntile)*32+slot)*2 + t2
//   slot = ((n_in<<2)|kj)^ntile,  k = kt*32 + 8*ks + 4*t2 + kj ... (kin encoding)
__global__ __launch_bounds__(256) void pack_b_kernel(
    const float* __restrict__ B, uint32_t* __restrict__ P, int K, int N) {
  const int nq = N >> 2;
  const int idx = blockIdx.x * 256 + threadIdx.x;
  if (idx >= K * nq) return;
  const int k = idx / nq;
  const int n = (idx - k * nq) << 2;
  float4 v = *(const float4*)(B + (size_t)k * N + n);
  const int kt = k >> 5, kin = k & 31;
  const int ks = kin >> 3, kj = kin & 3, t2 = (kin >> 2) & 1;
  const int nband = n >> 7, nloc = n & 127;
  uint32_t* tb = P + ((size_t)(nband * (K >> 5) + kt)) * 4096;
  const float vv[4] = {v.x, v.y, v.z, v.w};
#pragma unroll
  for (int q = 0; q < 4; q++) {
    const int n_g = nloc + q;
    const int ntile = n_g >> 3, n_in = n_g & 7;
    const int slot = ((n_in << 2) | kj) ^ ntile;
    tb[((ks * 16 + ntile) * 32 + slot) * 2 + t2] = f2tf32(vv[q]);
  }
}

// ---------------- packed tf32 GEMM: C = A[M,K] * B[K,N] --------------------
// 128x128 tile, BK=32, 256 threads, cp.async 2-stage double buffer.
#define GEMM_SMEM (2 * 8192 * 4)
__global__ __launch_bounds__(256) void gemm_packed_kernel(
    const uint32_t* __restrict__ Ap, const uint32_t* __restrict__ Bp,
    float* __restrict__ C, int M, int N, int K) {
  extern __shared__ uint32_t sm[];  // [2][8192]: A tile 4096 w, B tile 4096 w
  const int tid = threadIdx.x;
  const int l = tid & 31;
  const int w = tid >> 5;
  const int warp_m = w >> 2;
  const int warp_n = w & 3;
  const int niter = K >> 5;

  const uint4* Ag = (const uint4*)(Ap + (size_t)blockIdx.y * niter * 4096);
  const uint4* Bg = (const uint4*)(Bp + (size_t)blockIdx.x * niter * 4096);
  const uint32_t smu = (uint32_t)__cvta_generic_to_shared(sm);

  float acc[4][4][4];
#pragma unroll
  for (int mt = 0; mt < 4; mt++)
#pragma unroll
    for (int nt = 0; nt < 4; nt++)
#pragma unroll
      for (int c = 0; c < 4; c++) acc[mt][nt][c] = 0.0f;

  // prologue: stage 0
  {
    const uint4* ga = Ag;
    const uint4* gb = Bg;
#pragma unroll
    for (int j = 0; j < 4; j++) {
      cp16(smu + (tid + 256 * j) * 16, ga + tid + 256 * j);
      cp16(smu + 16384 + (tid + 256 * j) * 16, gb + tid + 256 * j);
    }
    asm volatile("cp.async.commit_group;");
  }

  for (int kt = 0; kt < niter; kt++) {
    if (kt + 1 < niter) {
      const uint32_t sb = smu + ((kt + 1) & 1) * 32768;
      const uint4* ga = Ag + (size_t)(kt + 1) * 1024;
      const uint4* gb = Bg + (size_t)(kt + 1) * 1024;
#pragma unroll
      for (int j = 0; j < 4; j++) {
        cp16(sb + (tid + 256 * j) * 16, ga + tid + 256 * j);
        cp16(sb + 16384 + (tid + 256 * j) * 16, gb + tid + 256 * j);
      }
      asm volatile("cp.async.commit_group;");
      asm volatile("cp.async.wait_group 1;");
    } else {
      asm volatile("cp.async.wait_group 0;");
    }
    __syncthreads();

    const uint32_t* smA = sm + (kt & 1) * 8192;
    const uint32_t* smB = smA + 4096;
#pragma unroll
    for (int ks = 0; ks < 4; ks++) {
      uint4 af[4];
      uint2 bf[4];
#pragma unroll
      for (int mt = 0; mt < 4; mt++) {
        const int mtile = warp_m * 4 + mt;
        af[mt] = ((const uint4*)smA)[(ks * 8 + mtile) * 32 + (l ^ ks)];
      }
#pragma unroll
      for (int nt = 0; nt < 4; nt++) {
        const int ntile = warp_n * 4 + nt;
        bf[nt] = ((const uint2*)smB)[(ks * 16 + ntile) * 32 + (l ^ ntile)];
      }
#pragma unroll
      for (int mt = 0; mt < 4; mt++) {
        const uint32_t a[4] = {af[mt].x, af[mt].y, af[mt].z, af[mt].w};
#pragma unroll
        for (int nt = 0; nt < 4; nt++) {
          const uint32_t b[2] = {bf[nt].x, bf[nt].y};
          mma_tf32(acc[mt][nt], a, b);
        }
      }
    }
    __syncthreads();
  }

  const int bm = blockIdx.y * 128;
  const int bn = blockIdx.x * 128;
#pragma unroll
  for (int mt = 0; mt < 4; mt++) {
    const int row = bm + warp_m * 64 + mt * 16 + (l >> 2);
#pragma unroll
    for (int nt = 0; nt < 4; nt++) {
      const int col = bn + warp_n * 32 + nt * 8 + 2 * (l & 3);
      float2 lo = {acc[mt][nt][0], acc[mt][nt][1]};
      float2 hi = {acc[mt][nt][2], acc[mt][nt][3]};
      *(float2*)(C + (size_t)row * N + col) = lo;
      *(float2*)(C + (size_t)(row + 8) * N + col) = hi;
    }
  }
}

// ---------------- RoPE -----------------------------------------------------
__global__ void rope_kernel(float* __restrict__ q, float* __restrict__ k) {
  const int s = blockIdx.x;
  const int hh = blockIdx.y;
  const int d = threadIdx.x;   // 0..63
  float* ptr;
  if (hh < NH) ptr = q + (size_t)s * DM + hh * HD;
  else         ptr = k + (size_t)s * (NKV * HD) + (hh - NH) * HD;
  float inv = powf(10000.0f, -((float)(2 * d) / 128.0f));
  float ang = (float)s * inv;
  float sn, c;
  sincosf(ang, &sn, &c);
  float x0 = ptr[d];
  float x1 = ptr[d + 64];
  ptr[d]      = x0 * c - x1 * sn;
  ptr[d + 64] = x1 * c + x0 * sn;
}

// ---------------- Flash attention on tensor cores (tf32 mma) ----------------
// (unchanged from round 3 — verified)
#define BQ 128
#define BKV 64
#define F_SMEM_WORDS (16384 + 8192 + 8704 + 8704)
#define F_SMEM_BYTES (F_SMEM_WORDS * 4)

__global__ __launch_bounds__(256, 1) void flash_mma_kernel(
    const float* __restrict__ Q, const float* __restrict__ K,
    const float* __restrict__ V, float* __restrict__ Og) {
  extern __shared__ uint4 smem4[];
  uint32_t* Qw = (uint32_t*)smem4;
  uint32_t* Kw = Qw + 16384;
  uint32_t* Vf = Kw + 8192;
  uint32_t* Ps = Vf + 8704;

  const int h  = blockIdx.y;
  const int qb = gridDim.x - 1 - blockIdx.x;
  const int q0 = qb * BQ;
  const int kvh = h >> 2;
  const int tid = threadIdx.x;
  const int l = tid & 31;
  const int w = tid >> 5;

  const int lq = l >> 2;
  const int lc = l & 3;

  {
    const int ks = l >> 1, pair = l & 1;
#pragma unroll
    for (int i = 0; i < 16; i++) {
      const int row = w + 8 * i;
      float4 qv = *(const float4*)(Q + (size_t)(q0 + row) * DM + h * HD + 4 * l);
      const int mt = row >> 4, half = (row >> 3) & 1;
      const int slot = (row & 7) ^ (ks & 7);
      uint4 u = {f2tf32(qv.x), f2tf32(qv.y), f2tf32(qv.z), f2tf32(qv.w)};
      smem4[(((ks * 8 + mt) * 2 + pair) * 2 + half) * 8 + slot] = u;
    }
  }

  float m_i0 = -3.0e38f, m_i1 = -3.0e38f;
  float l_i0 = 0.0f, l_i1 = 0.0f;
  float O[16][4];
#pragma unroll
  for (int nt = 0; nt < 16; nt++)
#pragma unroll
    for (int c = 0; c < 4; c++) O[nt][c] = 0.0f;

  __syncthreads();

  const int ntiles = (q0 + BQ) / BKV;
  const float scale = 0.08838834764831845f;
  const int psbase = w * 1088;

  for (int t = 0; t < ntiles; t++) {
    __syncthreads();
    {
      const int ks = l >> 1, pair = l & 1;
#pragma unroll
      for (int i = 0; i < 8; i++) {
        const int row = w + 8 * i;
        float4 kv4 = *(const float4*)(K + (size_t)(t * BKV + row) * (NKV * HD) +
                                      kvh * HD + 4 * l);
        const int nt = row >> 3;
        const int slot = (row & 7) ^ (ks & 7);
        uint4 u = {f2tf32(kv4.x), f2tf32(kv4.y), f2tf32(kv4.z), f2tf32(kv4.w)};
        ((uint4*)Kw)[((ks * 8 + nt) * 2 + pair) * 8 + slot] = u;
      }
    }
    {
      const int ntv = l >> 1;
      const int nbase = 4 * (l & 1);
#pragma unroll
      for (int i = 0; i < 8; i++) {
        const int row = w + 8 * i;
        float4 vv = *(const float4*)(V + (size_t)(t * BKV + row) * (NKV * HD) +
                                     kvh * HD + 4 * l);
        const int ksv = row >> 3, pair = (row >> 2) & 1, kj = row & 3;
        uint32_t* base = Vf + (ksv * 16 + ntv) * 68 + pair * 32 + kj;
        base[(nbase + 0) * 4] = f2tf32(vv.x);
        base[(nbase + 1) * 4] = f2tf32(vv.y);
        base[(nbase + 2) * 4] = f2tf32(vv.z);
        base[(nbase + 3) * 4] = f2tf32(vv.w);
      }
    }
    __syncthreads();

    const bool active = (t * BKV <= q0 + 16 * w + 15);
    if (active) {
      float S[8][4];
#pragma unroll
      for (int nt = 0; nt < 8; nt++)
#pragma unroll
        for (int c = 0; c < 4; c++) S[nt][c] = 0.0f;

#pragma unroll
      for (int ks = 0; ks < 16; ks++) {
        const int sl = lq ^ (ks & 7);
        const int qbas = ((ks * 8 + w) * 32 + sl) * 4 + lc;
        uint32_t a[4];
        a[0] = Qw[qbas];
        a[1] = Qw[qbas + 32];
        a[2] = Qw[qbas + 64];
        a[3] = Qw[qbas + 96];
#pragma unroll
        for (int nt = 0; nt < 8; nt++) {
          const int kbas = ((ks * 8 + nt) * 16 + sl) * 4 + lc;
          uint32_t b[2];
          b[0] = Kw[kbas];
          b[1] = Kw[kbas + 32];
          mma_tf32(S[nt], a, b);
        }
      }

#pragma unroll
      for (int nt = 0; nt < 8; nt++)
#pragma unroll
        for (int c = 0; c < 4; c++) S[nt][c] *= scale;

      const int rowg0 = q0 + 16 * w + lq;
      const int rowg1 = rowg0 + 8;
      if (t * BKV + BKV - 1 > q0 + 16 * w) {
#pragma unroll
        for (int nt = 0; nt < 8; nt++) {
          const int c0 = t * BKV + nt * 8 + 2 * lc;
          if (c0 > rowg0)     S[nt][0] = -3.0e38f;
          if (c0 + 1 > rowg0) S[nt][1] = -3.0e38f;
          if (c0 > rowg1)     S[nt][2] = -3.0e38f;
          if (c0 + 1 > rowg1) S[nt][3] = -3.0e38f;
        }
      }

      float mx0 = -3.0e38f, mx1 = -3.0e38f;
#pragma unroll
      for (int nt = 0; nt < 8; nt++) {
        mx0 = fmaxf(mx0, fmaxf(S[nt][0], S[nt][1]));
        mx1 = fmaxf(mx1, fmaxf(S[nt][2], S[nt][3]));
      }
      mx0 = fmaxf(mx0, __shfl_xor_sync(0xffffffffu, mx0, 1));
      mx0 = fmaxf(mx0, __shfl_xor_sync(0xffffffffu, mx0, 2));
      mx1 = fmaxf(mx1, __shfl_xor_sync(0xffffffffu, mx1, 1));
      mx1 = fmaxf(mx1, __shfl_xor_sync(0xffffffffu, mx1, 2));
      const float mn0 = fmaxf(m_i0, mx0);
      const float mn1 = fmaxf(m_i1, mx1);

      float rs0 = 0.0f, rs1 = 0.0f;
      const int ps0 = psbase + lq * 68 + 2 * lc;
      const int ps1 = psbase + (lq + 8) * 68 + 2 * lc;
#pragma unroll
      for (int nt = 0; nt < 8; nt++) {
        float p0 = __expf(S[nt][0] - mn0);
        float p1 = __expf(S[nt][1] - mn0);
        float p2 = __expf(S[nt][2] - mn1);
        float p3 = __expf(S[nt][3] - mn1);
        rs0 += p0 + p1;
        rs1 += p2 + p3;
        Ps[ps0 + nt * 8]     = f2tf32(p0);
        Ps[ps0 + nt * 8 + 1] = f2tf32(p1);
        Ps[ps1 + nt * 8]     = f2tf32(p2);
        Ps[ps1 + nt * 8 + 1] = f2tf32(p3);
      }
      rs0 += __shfl_xor_sync(0xffffffffu, rs0, 1);
      rs0 += __shfl_xor_sync(0xffffffffu, rs0, 2);
      rs1 += __shfl_xor_sync(0xffffffffu, rs1, 1);
      rs1 += __shfl_xor_sync(0xffffffffu, rs1, 2);
      const float alpha0 = __expf(m_i0 - mn0);
      const float alpha1 = __expf(m_i1 - mn1);
      l_i0 = l_i0 * alpha0 + rs0;
      l_i1 = l_i1 * alpha1 + rs1;
      m_i0 = mn0;
      m_i1 = mn1;
#pragma unroll
      for (int nt = 0; nt < 16; nt++) {
        O[nt][0] *= alpha0;
        O[nt][1] *= alpha0;
        O[nt][2] *= alpha1;
        O[nt][3] *= alpha1;
      }
      __syncwarp();

#pragma unroll
      for (int ks = 0; ks < 8; ks++) {
        uint32_t a[4];
        const int pa0 = psbase + lq * 68 + ks * 8 + lc;
        a[0] = Ps[pa0];
        a[1] = Ps[pa0 + 544];
        a[2] = Ps[pa0 + 4];
        a[3] = Ps[pa0 + 548];
#pragma unroll
        for (int nt = 0; nt < 16; nt++) {
          const int vb = (ks * 16 + nt) * 68 + lq * 4 + lc;
          uint32_t b[2];
          b[0] = Vf[vb];
          b[1] = Vf[vb + 32];
          mma_tf32(O[nt], a, b);
        }
      }
      __syncwarp();
    }
  }

  const float inv0 = 1.0f / l_i0;
  const float inv1 = 1.0f / l_i1;
  const int row0 = q0 + 16 * w + lq;
#pragma unroll
  for (int nt = 0; nt < 16; nt++) {
    const int col = h * HD + nt * 8 + 2 * lc;
    float2 v0 = {O[nt][0] * inv0, O[nt][1] * inv0};
    float2 v1 = {O[nt][2] * inv1, O[nt][3] * inv1};
    *(float2*)(Og + (size_t)row0 * DM + col) = v0;
    *(float2*)(Og + (size_t)(row0 + 8) * DM + col) = v1;
  }
}

// ---------------- launch ----------------------------------------------------
extern "C" void kernel_launch(void* const* d_in, const int* in_sizes, int n_in,
                              void* d_out, int out_size) {
  const float* x  = (const float*)d_in[0];
  const float* wq = (const float*)d_in[1];
  const float* wk = (const float*)d_in[2];
  const float* wv = (const float*)d_in[3];
  const float* wo = (const float*)d_in[4];
  float* out = (float*)d_out;

  float *q_p, *k_p, *v_p, *a_p;
  uint32_t *px, *pattn, *pwq, *pwk, *pwv, *pwo;
  cudaGetSymbolAddress((void**)&q_p, g_q);
  cudaGetSymbolAddress((void**)&k_p, g_k);
  cudaGetSymbolAddress((void**)&v_p, g_v);
  cudaGetSymbolAddress((void**)&a_p, g_attn);
  cudaGetSymbolAddress((void**)&px, g_px);
  cudaGetSymbolAddress((void**)&pattn, g_pattn);
  cudaGetSymbolAddress((void**)&pwq, g_pwq);
  cudaGetSymbolAddress((void**)&pwk, g_pwk);
  cudaGetSymbolAddress((void**)&pwv, g_pwv);
  cudaGetSymbolAddress((void**)&pwo, g_pwo);

  cudaFuncSetAttribute(gemm_packed_kernel,
                       cudaFuncAttributeMaxDynamicSharedMemorySize, GEMM_SMEM);
  cudaFuncSetAttribute(flash_mma_kernel,
                       cudaFuncAttributeMaxDynamicSharedMemorySize, F_SMEM_BYTES);

  // pack inputs into fragment layouts
  pack_a_kernel<<<(S_LEN * DM / 4 + 255) / 256, 256>>>(x, px, S_LEN, DM);
  pack_b_kernel<<<(DM * DM / 4 + 255) / 256, 256>>>(wq, pwq, DM, DM);
  pack_b_kernel<<<(DM * NKV * HD / 4 + 255) / 256, 256>>>(wk, pwk, DM, NKV * HD);
  pack_b_kernel<<<(DM * NKV * HD / 4 + 255) / 256, 256>>>(wv, pwv, DM, NKV * HD);
  pack_b_kernel<<<(DM * DM / 4 + 255) / 256, 256>>>(wo, pwo, DM, DM);

  // QKV projections (packed tf32 tensor cores)
  gemm_packed_kernel<<<dim3(DM / 128, S_LEN / 128), 256, GEMM_SMEM>>>(
      px, pwq, q_p, S_LEN, DM, DM);
  gemm_packed_kernel<<<dim3((NKV * HD) / 128, S_LEN / 128), 256, GEMM_SMEM>>>(
      px, pwk, k_p, S_LEN, NKV * HD, DM);
  gemm_packed_kernel<<<dim3((NKV * HD) / 128, S_LEN / 128), 256, GEMM_SMEM>>>(
      px, pwv, v_p, S_LEN, NKV * HD, DM);

  // RoPE on q and k
  rope_kernel<<<dim3(S_LEN, NH + NKV), 64>>>(q_p, k_p);

  // causal flash attention (tf32 tensor cores)
  flash_mma_kernel<<<dim3(S_LEN / BQ, NH), 256, F_SMEM_BYTES>>>(q_p, k_p, v_p, a_p);

  // pack attention output, then output projection
  pack_a_kernel<<<(S_LEN * DM / 4 + 255) / 256, 256>>>(a_p, pattn, S_LEN, DM);
  gemm_packed_kernel<<<dim3(DM / 128, S_LEN / 128), 256, GEMM_SMEM>>>(
      pattn, pwo, out, S_LEN, DM, DM);
}

// round 6
// speedup vs baseline: 4.5047x; 1.2960x over previous
#include <cuda_runtime.h>
#include <cuda_fp16.h>
#include <math.h>
#include <stdint.h>

#define S_LEN  4096
#define DM     2048
#define NH     16
#define NKV    4
#define HD     128
#define QKVW   3072          // fused qkv width

// ---------------- scratch (device globals; no runtime alloc allowed) --------
__device__ float g_qkv[(size_t)S_LEN * QKVW];          // 48 MB  q|k|v fused
__device__ float g_attn[(size_t)S_LEN * DM];           // 32 MB
__device__ uint4 g_pa[(size_t)S_LEN * DM / 8];         // packed x (fp16 A blobs)
__device__ uint4 g_pattn[(size_t)S_LEN * DM / 8];      // packed attn
__device__ uint2 g_pbqkv[(size_t)QKVW * DM / 4];       // packed wq|wk|wv (B blobs)
__device__ uint2 g_pbwo[(size_t)DM * DM / 4];          // packed wo

// ---------------- helpers ----------------------------------------------------
__device__ __forceinline__ uint32_t f2tf32(float x) {
  uint32_t u;
  asm("cvt.rna.tf32.f32 %0, %1;" : "=r"(u) : "f"(x));
  return u;
}

__device__ __forceinline__ uint32_t f2h2(float a, float b) {
  __half2 h = __floats2half2_rn(a, b);   // x=a (low), y=b (high)
  return *(uint32_t*)&h;
}

__device__ __forceinline__ void mma_tf32(float* c, const uint32_t* a,
                                         const uint32_t* b) {
  asm volatile(
      "mma.sync.aligned.m16n8k8.row.col.f32.tf32.tf32.f32 "
      "{%0,%1,%2,%3}, {%4,%5,%6,%7}, {%8,%9}, {%0,%1,%2,%3};"
      : "+f"(c[0]), "+f"(c[1]), "+f"(c[2]), "+f"(c[3])
      : "r"(a[0]), "r"(a[1]), "r"(a[2]), "r"(a[3]), "r"(b[0]), "r"(b[1]));
}

__device__ __forceinline__ void mma_f16(float* c, const uint32_t* a,
                                        const uint32_t* b) {
  asm volatile(
      "mma.sync.aligned.m16n8k16.row.col.f32.f16.f16.f32 "
      "{%0,%1,%2,%3}, {%4,%5,%6,%7}, {%8,%9}, {%0,%1,%2,%3};"
      : "+f"(c[0]), "+f"(c[1]), "+f"(c[2]), "+f"(c[3])
      : "r"(a[0]), "r"(a[1]), "r"(a[2]), "r"(a[3]), "r"(b[0]), "r"(b[1]));
}

__device__ __forceinline__ void cp16(uint32_t s, const void* g) {
  asm volatile("cp.async.cg.shared.global [%0], [%1], 16;" ::"r"(s), "l"(g));
}

__device__ __forceinline__ uint32_t smem_u32(const void* p) {
  uint32_t a;
  asm("{ .reg .u64 t; cvta.to.shared.u64 t, %1; cvt.u32.u64 %0, t; }"
      : "=r"(a) : "l"(p));
  return a;
}

// ---------------- fp16 pack kernels -----------------------------------------
// A blob per (mband, kt64): [s4][mtile8][lane32] x uint4 = 16 KB
//   lane l: g=l>>2, t=l&3; a0={A[g][2t],A[g][2t+1]}, a1=rows+8, a2=cols+8, a3=both
__global__ __launch_bounds__(256) void pack_a_f16(const float* __restrict__ A,
                                                  uint4* __restrict__ P, int K) {
  const int kt = blockIdx.x, mb = blockIdx.y, tid = threadIdx.x;
  const int T = gridDim.x;
  uint4* out = P + ((size_t)mb * T + kt) * 1024;
#pragma unroll
  for (int idx = tid; idx < 1024; idx += 256) {
    const int s = idx >> 8, m = (idx >> 5) & 7, l = idx & 31;
    const int g = l >> 2, t = l & 3;
    const int row0 = mb * 128 + m * 16 + g;
    const int kb = kt * 64 + s * 16 + 2 * t;
    const float* r0 = A + (size_t)row0 * K + kb;
    const float* r1 = r0 + (size_t)8 * K;
    uint4 u;
    u.x = f2h2(r0[0], r0[1]);
    u.y = f2h2(r1[0], r1[1]);
    u.z = f2h2(r0[8], r0[9]);
    u.w = f2h2(r1[8], r1[9]);
    out[idx] = u;
  }
}

// B blob per (nband, kt64): [s4][ntile16][lane32] x uint2 = 16 KB
//   lane l: t=l&3, c=n*8+(l>>2); b0={W[2t][c],W[2t+1][c]}, b1=k+8
__global__ __launch_bounds__(256) void pack_b_f16(const float* __restrict__ W,
                                                  uint2* __restrict__ P, int Nin,
                                                  int noff) {
  const int kt = blockIdx.x, nb = blockIdx.y, tid = threadIdx.x;
  const int T = gridDim.x;
  uint2* out = P + ((size_t)(nb + noff) * T + kt) * 2048;
#pragma unroll
  for (int idx = tid; idx < 2048; idx += 256) {
    const int s = idx >> 9, n = (idx >> 5) & 15, l = idx & 31;
    const int t = l & 3;
    const int c = nb * 128 + n * 8 + (l >> 2);
    const int kb = kt * 64 + s * 16 + 2 * t;
    const float* w0 = W + (size_t)kb * Nin + c;
    uint2 u;
    u.x = f2h2(w0[0], w0[Nin]);
    u.y = f2h2(w0[(size_t)8 * Nin], w0[(size_t)9 * Nin]);
    out[idx] = u;
  }
}

// ---------------- packed fp16 GEMM: C = A[M,K] * B[K,N] ---------------------
// 128x128 tile, BK=64, 256 threads, cp.async 2-stage double buffer.
#define GEMM_SMEM (2 * 32768)
__global__ __launch_bounds__(256) void gemm_f16(const uint4* __restrict__ Ap,
                                                const uint2* __restrict__ Bp,
                                                float* __restrict__ C, int N,
                                                int K) {
  extern __shared__ uint32_t sm[];
  const int tid = threadIdx.x;
  const int l = tid & 31;
  const int w = tid >> 5;
  const int warp_m = w >> 2;   // 0..1
  const int warp_n = w & 3;    // 0..3
  const int T = K >> 6;

  const uint4* Ag = Ap + (size_t)blockIdx.y * T * 1024;
  const uint4* Bg = (const uint4*)(Bp + (size_t)blockIdx.x * T * 2048);
  const uint32_t smu = smem_u32(sm);

  float acc[4][4][4];
#pragma unroll
  for (int mt = 0; mt < 4; mt++)
#pragma unroll
    for (int nt = 0; nt < 4; nt++)
#pragma unroll
      for (int c = 0; c < 4; c++) acc[mt][nt][c] = 0.0f;

#define CPT(t)                                                                 \
  do {                                                                         \
    const uint32_t ba = smu + ((t) & 1) * 32768;                               \
    const uint4* ga = Ag + (size_t)(t) * 1024;                                 \
    const uint4* gb = Bg + (size_t)(t) * 1024;                                 \
    _Pragma("unroll") for (int j = 0; j < 4; j++) {                            \
      cp16(ba + (tid + 256 * j) * 16, ga + tid + 256 * j);                     \
      cp16(ba + 16384 + (tid + 256 * j) * 16, gb + tid + 256 * j);             \
    }                                                                          \
    asm volatile("cp.async.commit_group;");                                    \
  } while (0)

  CPT(0);

  for (int t = 0; t < T; t++) {
    if (t + 1 < T) {
      CPT(t + 1);
      asm volatile("cp.async.wait_group 1;");
    } else {
      asm volatile("cp.async.wait_group 0;");
    }
    __syncthreads();

    const uint4* smA = (const uint4*)(sm + (t & 1) * 8192);
    const uint2* smB = (const uint2*)(sm + (t & 1) * 8192 + 4096);
#pragma unroll
    for (int s = 0; s < 4; s++) {
      uint4 af[4];
      uint2 bf[4];
#pragma unroll
      for (int mt = 0; mt < 4; mt++)
        af[mt] = smA[(s * 8 + warp_m * 4 + mt) * 32 + l];
#pragma unroll
      for (int nt = 0; nt < 4; nt++)
        bf[nt] = smB[(s * 16 + warp_n * 4 + nt) * 32 + l];
#pragma unroll
      for (int mt = 0; mt < 4; mt++) {
        const uint32_t a[4] = {af[mt].x, af[mt].y, af[mt].z, af[mt].w};
#pragma unroll
        for (int nt = 0; nt < 4; nt++) {
          const uint32_t b[2] = {bf[nt].x, bf[nt].y};
          mma_f16(acc[mt][nt], a, b);
        }
      }
    }
    __syncthreads();
  }

  const int bm = blockIdx.y * 128;
  const int bn = blockIdx.x * 128;
#pragma unroll
  for (int mt = 0; mt < 4; mt++) {
    const int row = bm + warp_m * 64 + mt * 16 + (l >> 2);
#pragma unroll
    for (int nt = 0; nt < 4; nt++) {
      const int col = bn + warp_n * 32 + nt * 8 + 2 * (l & 3);
      float2 lo = {acc[mt][nt][0], acc[mt][nt][1]};
      float2 hi = {acc[mt][nt][2], acc[mt][nt][3]};
      *(float2*)(C + (size_t)row * N + col) = lo;
      *(float2*)(C + (size_t)(row + 8) * N + col) = hi;
    }
  }
}

// ---------------- RoPE (on fused qkv buffer) --------------------------------
__global__ void rope_kernel(float* __restrict__ qkv) {
  const int s = blockIdx.x;
  const int hh = blockIdx.y;
  const int d = threadIdx.x;  // 0..63
  float* ptr = qkv + (size_t)s * QKVW +
               (hh < NH ? hh * HD : DM + (hh - NH) * HD);
  float inv = powf(10000.0f, -((float)(2 * d) / 128.0f));
  float ang = (float)s * inv;
  float sn, c;
  sincosf(ang, &sn, &c);
  float x0 = ptr[d];
  float x1 = ptr[d + 64];
  ptr[d] = x0 * c - x1 * sn;
  ptr[d + 64] = x1 * c + x0 * sn;
}

// ---------------- Flash attention on tensor cores (tf32 mma.sync) -----------
#define BQ 128
#define BKV 64
#define F_SMEM_WORDS (16384 + 8192 + 8704 + 8704)
#define F_SMEM_BYTES (F_SMEM_WORDS * 4)

__global__ __launch_bounds__(256, 1) void flash_mma_kernel(
    const float* __restrict__ QKV, float* __restrict__ Og) {
  extern __shared__ uint4 smem4[];
  uint32_t* Qw = (uint32_t*)smem4;
  uint32_t* Kw = Qw + 16384;
  uint32_t* Vf = Kw + 8192;
  uint32_t* Ps = Vf + 8704;

  const int h = blockIdx.y;
  const int qb = gridDim.x - 1 - blockIdx.x;
  const int q0 = qb * BQ;
  const int kvh = h >> 2;
  const int tid = threadIdx.x;
  const int l = tid & 31;
  const int w = tid >> 5;
  const int lq = l >> 2;
  const int lc = l & 3;

  const float* Qp = QKV + h * HD;
  const float* Kp = QKV + DM + kvh * HD;
  const float* Vp = QKV + DM + NKV * HD + kvh * HD;

  {
    const int ks = l >> 1, pair = l & 1;
#pragma unroll
    for (int i = 0; i < 16; i++) {
      const int row = w + 8 * i;
      float4 qv = *(const float4*)(Qp + (size_t)(q0 + row) * QKVW + 4 * l);
      const int mt = row >> 4, half = (row >> 3) & 1;
      const int slot = (row & 7) ^ (ks & 7);
      uint4 u = {f2tf32(qv.x), f2tf32(qv.y), f2tf32(qv.z), f2tf32(qv.w)};
      smem4[(((ks * 8 + mt) * 2 + pair) * 2 + half) * 8 + slot] = u;
    }
  }

  float m_i0 = -3.0e38f, m_i1 = -3.0e38f;
  float l_i0 = 0.0f, l_i1 = 0.0f;
  float O[16][4];
#pragma unroll
  for (int nt = 0; nt < 16; nt++)
#pragma unroll
    for (int c = 0; c < 4; c++) O[nt][c] = 0.0f;

  __syncthreads();

  const int ntiles = (q0 + BQ) / BKV;
  const float scale = 0.08838834764831845f;
  const int psbase = w * 1088;

  for (int t = 0; t < ntiles; t++) {
    __syncthreads();
    {
      const int ks = l >> 1, pair = l & 1;
#pragma unroll
      for (int i = 0; i < 8; i++) {
        const int row = w + 8 * i;
        float4 kv4 =
            *(const float4*)(Kp + (size_t)(t * BKV + row) * QKVW + 4 * l);
        const int nt = row >> 3;
        const int slot = (row & 7) ^ (ks & 7);
        uint4 u = {f2tf32(kv4.x), f2tf32(kv4.y), f2tf32(kv4.z), f2tf32(kv4.w)};
        ((uint4*)Kw)[((ks * 8 + nt) * 2 + pair) * 8 + slot] = u;
      }
    }
    {
      const int ntv = l >> 1;
      const int nbase = 4 * (l & 1);
#pragma unroll
      for (int i = 0; i < 8; i++) {
        const int row = w + 8 * i;
        float4 vv =
            *(const float4*)(Vp + (size_t)(t * BKV + row) * QKVW + 4 * l);
        const int ksv = row >> 3, pair = (row >> 2) & 1, kj = row & 3;
        uint32_t* base = Vf + (ksv * 16 + ntv) * 68 + pair * 32 + kj;
        base[(nbase + 0) * 4] = f2tf32(vv.x);
        base[(nbase + 1) * 4] = f2tf32(vv.y);
        base[(nbase + 2) * 4] = f2tf32(vv.z);
        base[(nbase + 3) * 4] = f2tf32(vv.w);
      }
    }
    __syncthreads();

    const bool active = (t * BKV <= q0 + 16 * w + 15);
    if (active) {
      float S[8][4];
#pragma unroll
      for (int nt = 0; nt < 8; nt++)
#pragma unroll
        for (int c = 0; c < 4; c++) S[nt][c] = 0.0f;

#pragma unroll
      for (int ks = 0; ks < 16; ks++) {
        const int sl = lq ^ (ks & 7);
        const int qbas = ((ks * 8 + w) * 32 + sl) * 4 + lc;
        uint32_t a[4];
        a[0] = Qw[qbas];
        a[1] = Qw[qbas + 32];
        a[2] = Qw[qbas + 64];
        a[3] = Qw[qbas + 96];
#pragma unroll
        for (int nt = 0; nt < 8; nt++) {
          const int kbas = ((ks * 8 + nt) * 16 + sl) * 4 + lc;
          uint32_t b[2];
          b[0] = Kw[kbas];
          b[1] = Kw[kbas + 32];
          mma_tf32(S[nt], a, b);
        }
      }

#pragma unroll
      for (int nt = 0; nt < 8; nt++)
#pragma unroll
        for (int c = 0; c < 4; c++) S[nt][c] *= scale;

      const int rowg0 = q0 + 16 * w + lq;
      const int rowg1 = rowg0 + 8;
      if (t * BKV + BKV - 1 > q0 + 16 * w) {
#pragma unroll
        for (int nt = 0; nt < 8; nt++) {
          const int c0 = t * BKV + nt * 8 + 2 * lc;
          if (c0 > rowg0) S[nt][0] = -3.0e38f;
          if (c0 + 1 > rowg0) S[nt][1] = -3.0e38f;
          if (c0 > rowg1) S[nt][2] = -3.0e38f;
          if (c0 + 1 > rowg1) S[nt][3] = -3.0e38f;
        }
      }

      float mx0 = -3.0e38f, mx1 = -3.0e38f;
#pragma unroll
      for (int nt = 0; nt < 8; nt++) {
        mx0 = fmaxf(mx0, fmaxf(S[nt][0], S[nt][1]));
        mx1 = fmaxf(mx1, fmaxf(S[nt][2], S[nt][3]));
      }
      mx0 = fmaxf(mx0, __shfl_xor_sync(0xffffffffu, mx0, 1));
      mx0 = fmaxf(mx0, __shfl_xor_sync(0xffffffffu, mx0, 2));
      mx1 = fmaxf(mx1, __shfl_xor_sync(0xffffffffu, mx1, 1));
      mx1 = fmaxf(mx1, __shfl_xor_sync(0xffffffffu, mx1, 2));
      const float mn0 = fmaxf(m_i0, mx0);
      const float mn1 = fmaxf(m_i1, mx1);

      float rs0 = 0.0f, rs1 = 0.0f;
      const int ps0 = psbase + lq * 68 + 2 * lc;
      const int ps1 = psbase + (lq + 8) * 68 + 2 * lc;
#pragma unroll
      for (int nt = 0; nt < 8; nt++) {
        float p0 = __expf(S[nt][0] - mn0);
        float p1 = __expf(S[nt][1] - mn0);
        float p2 = __expf(S[nt][2] - mn1);
        float p3 = __expf(S[nt][3] - mn1);
        rs0 += p0 + p1;
        rs1 += p2 + p3;
        Ps[ps0 + nt * 8] = f2tf32(p0);
        Ps[ps0 + nt * 8 + 1] = f2tf32(p1);
        Ps[ps1 + nt * 8] = f2tf32(p2);
        Ps[ps1 + nt * 8 + 1] = f2tf32(p3);
      }
      rs0 += __shfl_xor_sync(0xffffffffu, rs0, 1);
      rs0 += __shfl_xor_sync(0xffffffffu, rs0, 2);
      rs1 += __shfl_xor_sync(0xffffffffu, rs1, 1);
      rs1 += __shfl_xor_sync(0xffffffffu, rs1, 2);
      const float alpha0 = __expf(m_i0 - mn0);
      const float alpha1 = __expf(m_i1 - mn1);
      l_i0 = l_i0 * alpha0 + rs0;
      l_i1 = l_i1 * alpha1 + rs1;
      m_i0 = mn0;
      m_i1 = mn1;
#pragma unroll
      for (int nt = 0; nt < 16; nt++) {
        O[nt][0] *= alpha0;
        O[nt][1] *= alpha0;
        O[nt][2] *= alpha1;
        O[nt][3] *= alpha1;
      }
      __syncwarp();

#pragma unroll
      for (int ks = 0; ks < 8; ks++) {
        uint32_t a[4];
        const int pa0 = psbase + lq * 68 + ks * 8 + lc;
        a[0] = Ps[pa0];
        a[1] = Ps[pa0 + 544];
        a[2] = Ps[pa0 + 4];
        a[3] = Ps[pa0 + 548];
#pragma unroll
        for (int nt = 0; nt < 16; nt++) {
          const int vb = (ks * 16 + nt) * 68 + lq * 4 + lc;
          uint32_t b[2];
          b[0] = Vf[vb];
          b[1] = Vf[vb + 32];
          mma_tf32(O[nt], a, b);
        }
      }
      __syncwarp();
    }
  }

  const float inv0 = 1.0f / l_i0;
  const float inv1 = 1.0f / l_i1;
  const int row0 = q0 + 16 * w + lq;
#pragma unroll
  for (int nt = 0; nt < 16; nt++) {
    const int col = h * HD + nt * 8 + 2 * lc;
    float2 v0 = {O[nt][0] * inv0, O[nt][1] * inv0};
    float2 v1 = {O[nt][2] * inv1, O[nt][3] * inv1};
    *(float2*)(Og + (size_t)row0 * DM + col) = v0;
    *(float2*)(Og + (size_t)(row0 + 8) * DM + col) = v1;
  }
}

// ---------------- launch ----------------------------------------------------
extern "C" void kernel_launch(void* const* d_in, const int* in_sizes, int n_in,
                              void* d_out, int out_size) {
  const float* x = (const float*)d_in[0];
  const float* wq = (const float*)d_in[1];
  const float* wk = (const float*)d_in[2];
  const float* wv = (const float*)d_in[3];
  const float* wo = (const float*)d_in[4];
  float* out = (float*)d_out;

  float *qkv_p, *attn_p;
  uint4 *pa, *pattn;
  uint2 *pbqkv, *pbwo;
  cudaGetSymbolAddress((void**)&qkv_p, g_qkv);
  cudaGetSymbolAddress((void**)&attn_p, g_attn);
  cudaGetSymbolAddress((void**)&pa, g_pa);
  cudaGetSymbolAddress((void**)&pattn, g_pattn);
  cudaGetSymbolAddress((void**)&pbqkv, g_pbqkv);
  cudaGetSymbolAddress((void**)&pbwo, g_pbwo);

  cudaFuncSetAttribute(gemm_f16, cudaFuncAttributeMaxDynamicSharedMemorySize,
                       GEMM_SMEM);
  cudaFuncSetAttribute(flash_mma_kernel,
                       cudaFuncAttributeMaxDynamicSharedMemorySize,
                       F_SMEM_BYTES);

  // pack operands (fp16 fragment blobs)
  pack_a_f16<<<dim3(DM / 64, S_LEN / 128), 256>>>(x, pa, DM);
  pack_b_f16<<<dim3(DM / 64, 16), 256>>>(wq, pbqkv, DM, 0);
  pack_b_f16<<<dim3(DM / 64, 4), 256>>>(wk, pbqkv, NKV * HD, 16);
  pack_b_f16<<<dim3(DM / 64, 4), 256>>>(wv, pbqkv, NKV * HD, 20);
  pack_b_f16<<<dim3(DM / 64, 16), 256>>>(wo, pbwo, DM, 0);

  // fused QKV projection: [4096,2048] x [2048,3072]
  gemm_f16<<<dim3(QKVW / 128, S_LEN / 128), 256, GEMM_SMEM>>>(pa, pbqkv, qkv_p,
                                                              QKVW, DM);

  // RoPE on q and k (inside fused buffer)
  rope_kernel<<<dim3(S_LEN, NH + NKV), 64>>>(qkv_p);

  // causal flash attention (tf32 mma.sync)
  flash_mma_kernel<<<dim3(S_LEN / BQ, NH), 256, F_SMEM_BYTES>>>(qkv_p, attn_p);

  // output projection
  pack_a_f16<<<dim3(DM / 64, S_LEN / 128), 256>>>(attn_p, pattn, DM);
  gemm_f16<<<dim3(DM / 128, S_LEN / 128), 256, GEMM_SMEM>>>(pattn, pbwo, out,
                                                            DM, DM);
}

// round 7
// speedup vs baseline: 6.0778x; 1.3492x over previous
#include <cuda_runtime.h>
#include <cuda_fp16.h>
#include <math.h>
#include <stdint.h>

#define S_LEN  4096
#define DM     2048
#define NH     16
#define NKV    4
#define HD     128
#define QKVW   3072          // fused qkv width

// ---------------- scratch (device globals; no runtime alloc allowed) --------
__device__ float g_qkv[(size_t)S_LEN * QKVW];          // 48 MB  q|k|v fused
__device__ float g_attn[(size_t)S_LEN * DM];           // 32 MB
__device__ uint4 g_pa[(size_t)S_LEN * DM / 8];         // packed x (fp16 A blobs)
__device__ uint4 g_pattn[(size_t)S_LEN * DM / 8];      // packed attn
__device__ uint2 g_pbqkv[(size_t)QKVW * DM / 4];       // packed wq|wk|wv (B blobs)
__device__ uint2 g_pbwo[(size_t)DM * DM / 4];          // packed wo

// ---------------- helpers ----------------------------------------------------
__device__ __forceinline__ uint32_t f2h2(float a, float b) {
  __half2 h = __floats2half2_rn(a, b);   // x=a (low), y=b (high)
  return *(uint32_t*)&h;
}

__device__ __forceinline__ void mma_f16(float* c, const uint32_t* a,
                                        const uint32_t* b) {
  asm volatile(
      "mma.sync.aligned.m16n8k16.row.col.f32.f16.f16.f32 "
      "{%0,%1,%2,%3}, {%4,%5,%6,%7}, {%8,%9}, {%0,%1,%2,%3};"
      : "+f"(c[0]), "+f"(c[1]), "+f"(c[2]), "+f"(c[3])
      : "r"(a[0]), "r"(a[1]), "r"(a[2]), "r"(a[3]), "r"(b[0]), "r"(b[1]));
}

__device__ __forceinline__ void cp16(uint32_t s, const void* g) {
  asm volatile("cp.async.cg.shared.global [%0], [%1], 16;" ::"r"(s), "l"(g));
}

__device__ __forceinline__ uint32_t smem_u32(const void* p) {
  uint32_t a;
  asm("{ .reg .u64 t; cvta.to.shared.u64 t, %1; cvt.u32.u64 %0, t; }"
      : "=r"(a) : "l"(p));
  return a;
}

// ---------------- fp16 pack kernels -----------------------------------------
__global__ __launch_bounds__(256) void pack_a_f16(const float* __restrict__ A,
                                                  uint4* __restrict__ P, int K) {
  const int kt = blockIdx.x, mb = blockIdx.y, tid = threadIdx.x;
  const int T = gridDim.x;
  uint4* out = P + ((size_t)mb * T + kt) * 1024;
#pragma unroll
  for (int idx = tid; idx < 1024; idx += 256) {
    const int s = idx >> 8, m = (idx >> 5) & 7, l = idx & 31;
    const int g = l >> 2, t = l & 3;
    const int row0 = mb * 128 + m * 16 + g;
    const int kb = kt * 64 + s * 16 + 2 * t;
    const float* r0 = A + (size_t)row0 * K + kb;
    const float* r1 = r0 + (size_t)8 * K;
    uint4 u;
    u.x = f2h2(r0[0], r0[1]);
    u.y = f2h2(r1[0], r1[1]);
    u.z = f2h2(r0[8], r0[9]);
    u.w = f2h2(r1[8], r1[9]);
    out[idx] = u;
  }
}

__global__ __launch_bounds__(256) void pack_b_f16(const float* __restrict__ W,
                                                  uint2* __restrict__ P, int Nin,
                                                  int noff) {
  const int kt = blockIdx.x, nb = blockIdx.y, tid = threadIdx.x;
  const int T = gridDim.x;
  uint2* out = P + ((size_t)(nb + noff) * T + kt) * 2048;
#pragma unroll
  for (int idx = tid; idx < 2048; idx += 256) {
    const int s = idx >> 9, n = (idx >> 5) & 15, l = idx & 31;
    const int t = l & 3;
    const int c = nb * 128 + n * 8 + (l >> 2);
    const int kb = kt * 64 + s * 16 + 2 * t;
    const float* w0 = W + (size_t)kb * Nin + c;
    uint2 u;
    u.x = f2h2(w0[0], w0[Nin]);
    u.y = f2h2(w0[(size_t)8 * Nin], w0[(size_t)9 * Nin]);
    out[idx] = u;
  }
}

// ---------------- packed fp16 GEMM: C = A[M,K] * B[K,N] ---------------------
#define GEMM_SMEM (2 * 32768)
__global__ __launch_bounds__(256) void gemm_f16(const uint4* __restrict__ Ap,
                                                const uint2* __restrict__ Bp,
                                                float* __restrict__ C, int N,
                                                int K) {
  extern __shared__ uint32_t sm[];
  const int tid = threadIdx.x;
  const int l = tid & 31;
  const int w = tid >> 5;
  const int warp_m = w >> 2;
  const int warp_n = w & 3;
  const int T = K >> 6;

  const uint4* Ag = Ap + (size_t)blockIdx.y * T * 1024;
  const uint4* Bg = (const uint4*)(Bp + (size_t)blockIdx.x * T * 2048);
  const uint32_t smu = smem_u32(sm);

  float acc[4][4][4];
#pragma unroll
  for (int mt = 0; mt < 4; mt++)
#pragma unroll
    for (int nt = 0; nt < 4; nt++)
#pragma unroll
      for (int c = 0; c < 4; c++) acc[mt][nt][c] = 0.0f;

#define CPT(t)                                                                 \
  do {                                                                         \
    const uint32_t ba = smu + ((t) & 1) * 32768;                               \
    const uint4* ga = Ag + (size_t)(t) * 1024;                                 \
    const uint4* gb = Bg + (size_t)(t) * 1024;                                 \
    _Pragma("unroll") for (int j = 0; j < 4; j++) {                            \
      cp16(ba + (tid + 256 * j) * 16, ga + tid + 256 * j);                     \
      cp16(ba + 16384 + (tid + 256 * j) * 16, gb + tid + 256 * j);             \
    }                                                                          \
    asm volatile("cp.async.commit_group;");                                    \
  } while (0)

  CPT(0);

  for (int t = 0; t < T; t++) {
    if (t + 1 < T) {
      CPT(t + 1);
      asm volatile("cp.async.wait_group 1;");
    } else {
      asm volatile("cp.async.wait_group 0;");
    }
    __syncthreads();

    const uint4* smA = (const uint4*)(sm + (t & 1) * 8192);
    const uint2* smB = (const uint2*)(sm + (t & 1) * 8192 + 4096);
#pragma unroll
    for (int s = 0; s < 4; s++) {
      uint4 af[4];
      uint2 bf[4];
#pragma unroll
      for (int mt = 0; mt < 4; mt++)
        af[mt] = smA[(s * 8 + warp_m * 4 + mt) * 32 + l];
#pragma unroll
      for (int nt = 0; nt < 4; nt++)
        bf[nt] = smB[(s * 16 + warp_n * 4 + nt) * 32 + l];
#pragma unroll
      for (int mt = 0; mt < 4; mt++) {
        const uint32_t a[4] = {af[mt].x, af[mt].y, af[mt].z, af[mt].w};
#pragma unroll
        for (int nt = 0; nt < 4; nt++) {
          const uint32_t b[2] = {bf[nt].x, bf[nt].y};
          mma_f16(acc[mt][nt], a, b);
        }
      }
    }
    __syncthreads();
  }

  const int bm = blockIdx.y * 128;
  const int bn = blockIdx.x * 128;
#pragma unroll
  for (int mt = 0; mt < 4; mt++) {
    const int row = bm + warp_m * 64 + mt * 16 + (l >> 2);
#pragma unroll
    for (int nt = 0; nt < 4; nt++) {
      const int col = bn + warp_n * 32 + nt * 8 + 2 * (l & 3);
      float2 lo = {acc[mt][nt][0], acc[mt][nt][1]};
      float2 hi = {acc[mt][nt][2], acc[mt][nt][3]};
      *(float2*)(C + (size_t)row * N + col) = lo;
      *(float2*)(C + (size_t)(row + 8) * N + col) = hi;
    }
  }
}

// ---------------- RoPE (on fused qkv buffer) --------------------------------
__global__ void rope_kernel(float* __restrict__ qkv) {
  const int s = blockIdx.x;
  const int hh = blockIdx.y;
  const int d = threadIdx.x;  // 0..63
  float* ptr = qkv + (size_t)s * QKVW +
               (hh < NH ? hh * HD : DM + (hh - NH) * HD);
  float inv = powf(10000.0f, -((float)(2 * d) / 128.0f));
  float ang = (float)s * inv;
  float sn, c;
  sincosf(ang, &sn, &c);
  float x0 = ptr[d];
  float x1 = ptr[d + 64];
  ptr[d] = x0 * c - x1 * sn;
  ptr[d + 64] = x1 * c + x0 * sn;
}

// ---------------- Flash attention, fp16 m16n8k16 ----------------------------
// BQ=128 (8 warps x 16 rows), BKV=64, HD=128.
// Smem: Qf [ks8][mt8][l32] uint4 = 32KB ; Kf [ks8][nt8][l32] uint2 = 16KB ;
//       Vf [ks4][nt16][l32] uint2 = 16KB.  Total 64KB. P never touches smem.
#define BQ 128
#define BKV 64
#define F_SMEM_BYTES 65536

__global__ __launch_bounds__(256) void flash_f16_kernel(
    const float* __restrict__ QKV, float* __restrict__ Og) {
  extern __shared__ uint32_t fsm[];
  uint4* Qf = (uint4*)fsm;                 // 8192 words
  uint2* Kf = (uint2*)(fsm + 8192);        // 4096 words
  uint2* Vf = (uint2*)(fsm + 12288);       // 4096 words

  const int h = blockIdx.y;
  const int qb = gridDim.x - 1 - blockIdx.x;  // long blocks first
  const int q0 = qb * BQ;
  const int kvh = h >> 2;
  const int tid = threadIdx.x;
  const int l = tid & 31;
  const int w = tid >> 5;
  const int g = l >> 2;    // row group 0..7
  const int tt = l & 3;    // k/col group 0..3

  const float* Qp = QKV + h * HD;
  const float* Kp = QKV + DM + kvh * HD;
  const float* Vp = QKV + DM + NKV * HD + kvh * HD;
  const float scale = 0.08838834764831845f;  // folded into Q

  // ---- stage Q once: entry (ks=i, mt=w, l) at Qf[tid+256*i] ----
#pragma unroll
  for (int i = 0; i < 8; i++) {
    const float* r0 = Qp + (size_t)(q0 + 16 * w + g) * QKVW + 16 * i + 2 * tt;
    const float* r1 = r0 + (size_t)8 * QKVW;
    float2 x0 = *(const float2*)r0;
    float2 x1 = *(const float2*)(r0 + 8);
    float2 y0 = *(const float2*)r1;
    float2 y1 = *(const float2*)(r1 + 8);
    uint4 u;
    u.x = f2h2(x0.x * scale, x0.y * scale);
    u.y = f2h2(y0.x * scale, y0.y * scale);
    u.z = f2h2(x1.x * scale, x1.y * scale);
    u.w = f2h2(y1.x * scale, y1.y * scale);
    Qf[tid + 256 * i] = u;
  }

  float m_i0 = -3.0e38f, m_i1 = -3.0e38f;
  float l_i0 = 0.0f, l_i1 = 0.0f;
  float O[16][4];
#pragma unroll
  for (int nt = 0; nt < 16; nt++)
#pragma unroll
    for (int c = 0; c < 4; c++) O[nt][c] = 0.0f;

  const int ntiles = (q0 + BQ) / BKV;

  for (int t = 0; t < ntiles; t++) {
    __syncthreads();
    // ---- stage K: entry (ks=i, nt=w, l) at Kf[tid+256*i] ----
#pragma unroll
    for (int i = 0; i < 8; i++) {
      const float* kr =
          Kp + (size_t)(t * BKV + 8 * w + g) * QKVW + 16 * i + 2 * tt;
      float2 a0 = *(const float2*)kr;
      float2 a1 = *(const float2*)(kr + 8);
      uint2 u;
      u.x = f2h2(a0.x, a0.y);
      u.y = f2h2(a1.x, a1.y);
      Kf[tid + 256 * i] = u;
    }
    // ---- stage V: entry (ks=i>>1, nt=8*(i&1)+w, l) at Vf[tid+256*i] ----
#pragma unroll
    for (int i = 0; i < 8; i++) {
      const int ks = i >> 1, nt = 8 * (i & 1) + w;
      const int d = nt * 8 + g;
      const float* vr = Vp + (size_t)(t * BKV + ks * 16 + 2 * tt) * QKVW + d;
      uint2 u;
      u.x = f2h2(vr[0], vr[QKVW]);
      u.y = f2h2(vr[(size_t)8 * QKVW], vr[(size_t)9 * QKVW]);
      Vf[tid + 256 * i] = u;
    }
    __syncthreads();

    const bool active = (t * BKV <= q0 + 16 * w + 15);
    if (active) {
      // ---- S = (Q*scale) K^T : 8 ksteps x 8 ntiles ----
      float S[8][4];
#pragma unroll
      for (int nt = 0; nt < 8; nt++)
#pragma unroll
        for (int c = 0; c < 4; c++) S[nt][c] = 0.0f;
#pragma unroll
      for (int ks = 0; ks < 8; ks++) {
        uint4 af = Qf[(ks * 8 + w) * 32 + l];
        const uint32_t a[4] = {af.x, af.y, af.z, af.w};
#pragma unroll
        for (int nt = 0; nt < 8; nt++) {
          uint2 bf = Kf[(ks * 8 + nt) * 32 + l];
          const uint32_t b[2] = {bf.x, bf.y};
          mma_f16(S[nt], a, b);
        }
      }

      // ---- causal mask ----
      const int rowg0 = q0 + 16 * w + g;
      const int rowg1 = rowg0 + 8;
      if (t * BKV + BKV - 1 > q0 + 16 * w) {
#pragma unroll
        for (int nt = 0; nt < 8; nt++) {
          const int c0 = t * BKV + nt * 8 + 2 * tt;
          if (c0 > rowg0) S[nt][0] = -3.0e38f;
          if (c0 + 1 > rowg0) S[nt][1] = -3.0e38f;
          if (c0 > rowg1) S[nt][2] = -3.0e38f;
          if (c0 + 1 > rowg1) S[nt][3] = -3.0e38f;
        }
      }

      // ---- online softmax (exp written back into S) ----
      float mx0 = -3.0e38f, mx1 = -3.0e38f;
#pragma unroll
      for (int nt = 0; nt < 8; nt++) {
        mx0 = fmaxf(mx0, fmaxf(S[nt][0], S[nt][1]));
        mx1 = fmaxf(mx1, fmaxf(S[nt][2], S[nt][3]));
      }
      mx0 = fmaxf(mx0, __shfl_xor_sync(0xffffffffu, mx0, 1));
      mx0 = fmaxf(mx0, __shfl_xor_sync(0xffffffffu, mx0, 2));
      mx1 = fmaxf(mx1, __shfl_xor_sync(0xffffffffu, mx1, 1));
      mx1 = fmaxf(mx1, __shfl_xor_sync(0xffffffffu, mx1, 2));
      const float mn0 = fmaxf(m_i0, mx0);
      const float mn1 = fmaxf(m_i1, mx1);

      float rs0 = 0.0f, rs1 = 0.0f;
#pragma unroll
      for (int nt = 0; nt < 8; nt++) {
        S[nt][0] = __expf(S[nt][0] - mn0);
        S[nt][1] = __expf(S[nt][1] - mn0);
        S[nt][2] = __expf(S[nt][2] - mn1);
        S[nt][3] = __expf(S[nt][3] - mn1);
        rs0 += S[nt][0] + S[nt][1];
        rs1 += S[nt][2] + S[nt][3];
      }
      rs0 += __shfl_xor_sync(0xffffffffu, rs0, 1);
      rs0 += __shfl_xor_sync(0xffffffffu, rs0, 2);
      rs1 += __shfl_xor_sync(0xffffffffu, rs1, 1);
      rs1 += __shfl_xor_sync(0xffffffffu, rs1, 2);
      const float alpha0 = __expf(m_i0 - mn0);
      const float alpha1 = __expf(m_i1 - mn1);
      l_i0 = l_i0 * alpha0 + rs0;
      l_i1 = l_i1 * alpha1 + rs1;
      m_i0 = mn0;
      m_i1 = mn1;
#pragma unroll
      for (int nt = 0; nt < 16; nt++) {
        O[nt][0] *= alpha0;
        O[nt][1] *= alpha0;
        O[nt][2] *= alpha1;
        O[nt][3] *= alpha1;
      }

      // ---- O += P V : P fragments straight from registers ----
#pragma unroll
      for (int ks = 0; ks < 4; ks++) {
        const uint32_t a[4] = {f2h2(S[2 * ks][0], S[2 * ks][1]),
                               f2h2(S[2 * ks][2], S[2 * ks][3]),
                               f2h2(S[2 * ks + 1][0], S[2 * ks + 1][1]),
                               f2h2(S[2 * ks + 1][2], S[2 * ks + 1][3])};
#pragma unroll
        for (int nt = 0; nt < 16; nt++) {
          uint2 bf = Vf[(ks * 16 + nt) * 32 + l];
          const uint32_t b[2] = {bf.x, bf.y};
          mma_f16(O[nt], a, b);
        }
      }
    }
  }

  // ---- epilogue: normalize + store ----
  const float inv0 = 1.0f / l_i0;
  const float inv1 = 1.0f / l_i1;
  const int row0 = q0 + 16 * w + g;
#pragma unroll
  for (int nt = 0; nt < 16; nt++) {
    const int col = h * HD + nt * 8 + 2 * tt;
    float2 v0 = {O[nt][0] * inv0, O[nt][1] * inv0};
    float2 v1 = {O[nt][2] * inv1, O[nt][3] * inv1};
    *(float2*)(Og + (size_t)row0 * DM + col) = v0;
    *(float2*)(Og + (size_t)(row0 + 8) * DM + col) = v1;
  }
}

// ---------------- launch ----------------------------------------------------
extern "C" void kernel_launch(void* const* d_in, const int* in_sizes, int n_in,
                              void* d_out, int out_size) {
  const float* x = (const float*)d_in[0];
  const float* wq = (const float*)d_in[1];
  const float* wk = (const float*)d_in[2];
  const float* wv = (const float*)d_in[3];
  const float* wo = (const float*)d_in[4];
  float* out = (float*)d_out;

  float *qkv_p, *attn_p;
  uint4 *pa, *pattn;
  uint2 *pbqkv, *pbwo;
  cudaGetSymbolAddress((void**)&qkv_p, g_qkv);
  cudaGetSymbolAddress((void**)&attn_p, g_attn);
  cudaGetSymbolAddress((void**)&pa, g_pa);
  cudaGetSymbolAddress((void**)&pattn, g_pattn);
  cudaGetSymbolAddress((void**)&pbqkv, g_pbqkv);
  cudaGetSymbolAddress((void**)&pbwo, g_pbwo);

  cudaFuncSetAttribute(gemm_f16, cudaFuncAttributeMaxDynamicSharedMemorySize,
                       GEMM_SMEM);
  cudaFuncSetAttribute(flash_f16_kernel,
                       cudaFuncAttributeMaxDynamicSharedMemorySize,
                       F_SMEM_BYTES);

  // pack operands (fp16 fragment blobs)
  pack_a_f16<<<dim3(DM / 64, S_LEN / 128), 256>>>(x, pa, DM);
  pack_b_f16<<<dim3(DM / 64, 16), 256>>>(wq, pbqkv, DM, 0);
  pack_b_f16<<<dim3(DM / 64, 4), 256>>>(wk, pbqkv, NKV * HD, 16);
  pack_b_f16<<<dim3(DM / 64, 4), 256>>>(wv, pbqkv, NKV * HD, 20);
  pack_b_f16<<<dim3(DM / 64, 16), 256>>>(wo, pbwo, DM, 0);

  // fused QKV projection: [4096,2048] x [2048,3072]
  gemm_f16<<<dim3(QKVW / 128, S_LEN / 128), 256, GEMM_SMEM>>>(pa, pbqkv, qkv_p,
                                                              QKVW, DM);

  // RoPE on q and k (inside fused buffer)
  rope_kernel<<<dim3(S_LEN, NH + NKV), 64>>>(qkv_p);

  // causal flash attention (fp16 mma, register-direct P)
  flash_f16_kernel<<<dim3(S_LEN / BQ, NH), 256, F_SMEM_BYTES>>>(qkv_p, attn_p);

  // output projection
  pack_a_f16<<<dim3(DM / 64, S_LEN / 128), 256>>>(attn_p, pattn, DM);
  gemm_f16<<<dim3(DM / 128, S_LEN / 128), 256, GEMM_SMEM>>>(pattn, pbwo, out,
                                                            DM, DM);
}

// round 8
// speedup vs baseline: 6.3149x; 1.0390x over previous
#include <cuda_runtime.h>
#include <cuda_fp16.h>
#include <math.h>
#include <stdint.h>

#define S_LEN  4096
#define DM     2048
#define NH     16
#define NKV    4
#define HD     128
#define QKVW   3072          // fused qkv width

// ---------------- scratch (device globals; no runtime alloc allowed) --------
__device__ float g_qkv[(size_t)S_LEN * QKVW];          // 48 MB  q|k|v fused
__device__ uint4 g_pa[(size_t)S_LEN * DM / 8];         // packed x (fp16 A blobs)
__device__ uint4 g_pattn[(size_t)S_LEN * DM / 8];      // packed attn (A blobs)
__device__ uint2 g_pbqkv[(size_t)QKVW * DM / 4];       // packed wq|wk|wv
__device__ uint2 g_pbwo[(size_t)DM * DM / 4];          // packed wo
__device__ float2 g_rope[(size_t)S_LEN * 64];          // cos/sin table

// ---------------- helpers ----------------------------------------------------
__device__ __forceinline__ uint32_t f2h2(float a, float b) {
  __half2 h = __floats2half2_rn(a, b);   // x=a (low), y=b (high)
  return *(uint32_t*)&h;
}

__device__ __forceinline__ void mma_f16(float* c, const uint32_t* a,
                                        const uint32_t* b) {
  asm volatile(
      "mma.sync.aligned.m16n8k16.row.col.f32.f16.f16.f32 "
      "{%0,%1,%2,%3}, {%4,%5,%6,%7}, {%8,%9}, {%0,%1,%2,%3};"
      : "+f"(c[0]), "+f"(c[1]), "+f"(c[2]), "+f"(c[3])
      : "r"(a[0]), "r"(a[1]), "r"(a[2]), "r"(a[3]), "r"(b[0]), "r"(b[1]));
}

__device__ __forceinline__ void cp16(uint32_t s, const void* g) {
  asm volatile("cp.async.cg.shared.global [%0], [%1], 16;" ::"r"(s), "l"(g));
}

__device__ __forceinline__ uint32_t smem_u32(const void* p) {
  uint32_t a;
  asm("{ .reg .u64 t; cvta.to.shared.u64 t, %1; cvt.u32.u64 %0, t; }"
      : "=r"(a) : "l"(p));
  return a;
}

// ---------------- fp16 pack kernels -----------------------------------------
__global__ __launch_bounds__(256) void pack_a_f16(const float* __restrict__ A,
                                                  uint4* __restrict__ P, int K) {
  const int kt = blockIdx.x, mb = blockIdx.y, tid = threadIdx.x;
  const int T = gridDim.x;
  uint4* out = P + ((size_t)mb * T + kt) * 1024;
#pragma unroll
  for (int idx = tid; idx < 1024; idx += 256) {
    const int s = idx >> 8, m = (idx >> 5) & 7, l = idx & 31;
    const int g = l >> 2, t = l & 3;
    const int row0 = mb * 128 + m * 16 + g;
    const int kb = kt * 64 + s * 16 + 2 * t;
    const float* r0 = A + (size_t)row0 * K + kb;
    const float* r1 = r0 + (size_t)8 * K;
    uint4 u;
    u.x = f2h2(r0[0], r0[1]);
    u.y = f2h2(r1[0], r1[1]);
    u.z = f2h2(r0[8], r0[9]);
    u.w = f2h2(r1[8], r1[9]);
    out[idx] = u;
  }
}

__global__ __launch_bounds__(256) void pack_b_f16(const float* __restrict__ W,
                                                  uint2* __restrict__ P, int Nin,
                                                  int noff) {
  const int kt = blockIdx.x, nb = blockIdx.y, tid = threadIdx.x;
  const int T = gridDim.x;
  uint2* out = P + ((size_t)(nb + noff) * T + kt) * 2048;
#pragma unroll
  for (int idx = tid; idx < 2048; idx += 256) {
    const int s = idx >> 9, n = (idx >> 5) & 15, l = idx & 31;
    const int t = l & 3;
    const int c = nb * 128 + n * 8 + (l >> 2);
    const int kb = kt * 64 + s * 16 + 2 * t;
    const float* w0 = W + (size_t)kb * Nin + c;
    uint2 u;
    u.x = f2h2(w0[0], w0[Nin]);
    u.y = f2h2(w0[(size_t)8 * Nin], w0[(size_t)9 * Nin]);
    out[idx] = u;
  }
}

// ---------------- packed fp16 GEMM: 3-stage pipeline, 1 sync/iter -----------
#define GEMM_SMEM (3 * 32768)
__global__ __launch_bounds__(256) void gemm_f16(const uint4* __restrict__ Ap,
                                                const uint2* __restrict__ Bp,
                                                float* __restrict__ C, int N,
                                                int K) {
  extern __shared__ uint32_t sm[];
  const int tid = threadIdx.x;
  const int l = tid & 31;
  const int w = tid >> 5;
  const int warp_m = w >> 2;
  const int warp_n = w & 3;
  const int T = K >> 6;

  const uint4* Ag = Ap + (size_t)blockIdx.y * T * 1024;
  const uint4* Bg = (const uint4*)(Bp + (size_t)blockIdx.x * T * 2048);
  const uint32_t smu = smem_u32(sm);

  float acc[4][4][4];
#pragma unroll
  for (int mt = 0; mt < 4; mt++)
#pragma unroll
    for (int nt = 0; nt < 4; nt++)
#pragma unroll
      for (int c = 0; c < 4; c++) acc[mt][nt][c] = 0.0f;

#define CPT(t)                                                                 \
  do {                                                                         \
    const uint32_t ba = smu + ((t) % 3) * 32768;                               \
    const uint4* ga = Ag + (size_t)(t) * 1024;                                 \
    const uint4* gb = Bg + (size_t)(t) * 1024;                                 \
    _Pragma("unroll") for (int j = 0; j < 4; j++) {                            \
      cp16(ba + (tid + 256 * j) * 16, ga + tid + 256 * j);                     \
      cp16(ba + 16384 + (tid + 256 * j) * 16, gb + tid + 256 * j);             \
    }                                                                          \
    asm volatile("cp.async.commit_group;");                                    \
  } while (0)

  CPT(0);
  CPT(1);

  for (int t = 0; t < T; t++) {
    if (t + 1 < T)
      asm volatile("cp.async.wait_group 1;");
    else
      asm volatile("cp.async.wait_group 0;");
    __syncthreads();            // stage t ready; all warps done with t-1
    if (t + 2 < T) CPT(t + 2);  // safe: overwrites stage read at iter t-1

    const uint4* smA = (const uint4*)(sm + (t % 3) * 8192);
    const uint2* smB = (const uint2*)(sm + (t % 3) * 8192 + 4096);
#pragma unroll
    for (int s = 0; s < 4; s++) {
      uint4 af[4];
      uint2 bf[4];
#pragma unroll
      for (int mt = 0; mt < 4; mt++)
        af[mt] = smA[(s * 8 + warp_m * 4 + mt) * 32 + l];
#pragma unroll
      for (int nt = 0; nt < 4; nt++)
        bf[nt] = smB[(s * 16 + warp_n * 4 + nt) * 32 + l];
#pragma unroll
      for (int mt = 0; mt < 4; mt++) {
        const uint32_t a[4] = {af[mt].x, af[mt].y, af[mt].z, af[mt].w};
#pragma unroll
        for (int nt = 0; nt < 4; nt++) {
          const uint32_t b[2] = {bf[nt].x, bf[nt].y};
          mma_f16(acc[mt][nt], a, b);
        }
      }
    }
  }

  const int bm = blockIdx.y * 128;
  const int bn = blockIdx.x * 128;
#pragma unroll
  for (int mt = 0; mt < 4; mt++) {
    const int row = bm + warp_m * 64 + mt * 16 + (l >> 2);
#pragma unroll
    for (int nt = 0; nt < 4; nt++) {
      const int col = bn + warp_n * 32 + nt * 8 + 2 * (l & 3);
      float2 lo = {acc[mt][nt][0], acc[mt][nt][1]};
      float2 hi = {acc[mt][nt][2], acc[mt][nt][3]};
      *(float2*)(C + (size_t)row * N + col) = lo;
      *(float2*)(C + (size_t)(row + 8) * N + col) = hi;
    }
  }
}

// ---------------- RoPE: table + apply ----------------------------------------
__global__ __launch_bounds__(256) void rope_table_kernel() {
  const int idx = blockIdx.x * 256 + threadIdx.x;   // S_LEN*64 entries
  const int s = idx >> 6, d = idx & 63;
  float inv = powf(10000.0f, -((float)(2 * d) / 128.0f));
  float sn, cs;
  sincosf((float)s * inv, &sn, &cs);
  g_rope[idx] = make_float2(cs, sn);
}

__global__ __launch_bounds__(256) void rope_apply_kernel(float* __restrict__ qkv) {
  const int tid = threadIdx.x;
  const int d = tid & 63, si = tid >> 6;
  const int s = blockIdx.x * 4 + si;
  const int hh = blockIdx.y;
  float* ptr = qkv + (size_t)s * QKVW +
               (hh < NH ? hh * HD : DM + (hh - NH) * HD);
  const float2 cs = g_rope[s * 64 + d];
  const float x0 = ptr[d];
  const float x1 = ptr[d + 64];
  ptr[d] = x0 * cs.x - x1 * cs.y;
  ptr[d + 64] = x1 * cs.x + x0 * cs.y;
}

// ---------------- Flash attention, fp16 m16n8k16, packed-out epilogue -------
#define BQ 128
#define BKV 64
#define F_SMEM_BYTES 65536

__global__ __launch_bounds__(256) void flash_f16_kernel(
    const float* __restrict__ QKV, uint4* __restrict__ Pout) {
  extern __shared__ uint32_t fsm[];
  uint4* Qf = (uint4*)fsm;                 // 8192 words
  uint2* Kf = (uint2*)(fsm + 8192);        // 4096 words
  uint2* Vf = (uint2*)(fsm + 12288);       // 4096 words

  const int h = blockIdx.y;
  const int qb = gridDim.x - 1 - blockIdx.x;  // long blocks first
  const int q0 = qb * BQ;
  const int kvh = h >> 2;
  const int tid = threadIdx.x;
  const int l = tid & 31;
  const int w = tid >> 5;
  const int g = l >> 2;    // row group 0..7
  const int tt = l & 3;    // k/col group 0..3

  const float* Qp = QKV + h * HD;
  const float* Kp = QKV + DM + kvh * HD;
  const float* Vp = QKV + DM + NKV * HD + kvh * HD;
  const float scale = 0.08838834764831845f;  // folded into Q

#pragma unroll
  for (int i = 0; i < 8; i++) {
    const float* r0 = Qp + (size_t)(q0 + 16 * w + g) * QKVW + 16 * i + 2 * tt;
    const float* r1 = r0 + (size_t)8 * QKVW;
    float2 x0 = *(const float2*)r0;
    float2 x1 = *(const float2*)(r0 + 8);
    float2 y0 = *(const float2*)r1;
    float2 y1 = *(const float2*)(r1 + 8);
    uint4 u;
    u.x = f2h2(x0.x * scale, x0.y * scale);
    u.y = f2h2(y0.x * scale, y0.y * scale);
    u.z = f2h2(x1.x * scale, x1.y * scale);
    u.w = f2h2(y1.x * scale, y1.y * scale);
    Qf[tid + 256 * i] = u;
  }

  float m_i0 = -3.0e38f, m_i1 = -3.0e38f;
  float l_i0 = 0.0f, l_i1 = 0.0f;
  float O[16][4];
#pragma unroll
  for (int nt = 0; nt < 16; nt++)
#pragma unroll
    for (int c = 0; c < 4; c++) O[nt][c] = 0.0f;

  const int ntiles = (q0 + BQ) / BKV;

  for (int t = 0; t < ntiles; t++) {
    __syncthreads();
#pragma unroll
    for (int i = 0; i < 8; i++) {
      const float* kr =
          Kp + (size_t)(t * BKV + 8 * w + g) * QKVW + 16 * i + 2 * tt;
      float2 a0 = *(const float2*)kr;
      float2 a1 = *(const float2*)(kr + 8);
      uint2 u;
      u.x = f2h2(a0.x, a0.y);
      u.y = f2h2(a1.x, a1.y);
      Kf[tid + 256 * i] = u;
    }
#pragma unroll
    for (int i = 0; i < 8; i++) {
      const int ks = i >> 1, nt = 8 * (i & 1) + w;
      const int d = nt * 8 + g;
      const float* vr = Vp + (size_t)(t * BKV + ks * 16 + 2 * tt) * QKVW + d;
      uint2 u;
      u.x = f2h2(vr[0], vr[QKVW]);
      u.y = f2h2(vr[(size_t)8 * QKVW], vr[(size_t)9 * QKVW]);
      Vf[tid + 256 * i] = u;
    }
    __syncthreads();

    const bool active = (t * BKV <= q0 + 16 * w + 15);
    if (active) {
      float S[8][4];
#pragma unroll
      for (int nt = 0; nt < 8; nt++)
#pragma unroll
        for (int c = 0; c < 4; c++) S[nt][c] = 0.0f;
#pragma unroll
      for (int ks = 0; ks < 8; ks++) {
        uint4 af = Qf[(ks * 8 + w) * 32 + l];
        const uint32_t a[4] = {af.x, af.y, af.z, af.w};
#pragma unroll
        for (int nt = 0; nt < 8; nt++) {
          uint2 bf = Kf[(ks * 8 + nt) * 32 + l];
          const uint32_t b[2] = {bf.x, bf.y};
          mma_f16(S[nt], a, b);
        }
      }

      const int rowg0 = q0 + 16 * w + g;
      const int rowg1 = rowg0 + 8;
      if (t * BKV + BKV - 1 > q0 + 16 * w) {
#pragma unroll
        for (int nt = 0; nt < 8; nt++) {
          const int c0 = t * BKV + nt * 8 + 2 * tt;
          if (c0 > rowg0) S[nt][0] = -3.0e38f;
          if (c0 + 1 > rowg0) S[nt][1] = -3.0e38f;
          if (c0 > rowg1) S[nt][2] = -3.0e38f;
          if (c0 + 1 > rowg1) S[nt][3] = -3.0e38f;
        }
      }

      float mx0 = -3.0e38f, mx1 = -3.0e38f;
#pragma unroll
      for (int nt = 0; nt < 8; nt++) {
        mx0 = fmaxf(mx0, fmaxf(S[nt][0], S[nt][1]));
        mx1 = fmaxf(mx1, fmaxf(S[nt][2], S[nt][3]));
      }
      mx0 = fmaxf(mx0, __shfl_xor_sync(0xffffffffu, mx0, 1));
      mx0 = fmaxf(mx0, __shfl_xor_sync(0xffffffffu, mx0, 2));
      mx1 = fmaxf(mx1, __shfl_xor_sync(0xffffffffu, mx1, 1));
      mx1 = fmaxf(mx1, __shfl_xor_sync(0xffffffffu, mx1, 2));
      const float mn0 = fmaxf(m_i0, mx0);
      const float mn1 = fmaxf(m_i1, mx1);

      float rs0 = 0.0f, rs1 = 0.0f;
#pragma unroll
      for (int nt = 0; nt < 8; nt++) {
        S[nt][0] = __expf(S[nt][0] - mn0);
        S[nt][1] = __expf(S[nt][1] - mn0);
        S[nt][2] = __expf(S[nt][2] - mn1);
        S[nt][3] = __expf(S[nt][3] - mn1);
        rs0 += S[nt][0] + S[nt][1];
        rs1 += S[nt][2] + S[nt][3];
      }
      rs0 += __shfl_xor_sync(0xffffffffu, rs0, 1);
      rs0 += __shfl_xor_sync(0xffffffffu, rs0, 2);
      rs1 += __shfl_xor_sync(0xffffffffu, rs1, 1);
      rs1 += __shfl_xor_sync(0xffffffffu, rs1, 2);
      const float alpha0 = __expf(m_i0 - mn0);
      const float alpha1 = __expf(m_i1 - mn1);
      l_i0 = l_i0 * alpha0 + rs0;
      l_i1 = l_i1 * alpha1 + rs1;
      m_i0 = mn0;
      m_i1 = mn1;
#pragma unroll
      for (int nt = 0; nt < 16; nt++) {
        O[nt][0] *= alpha0;
        O[nt][1] *= alpha0;
        O[nt][2] *= alpha1;
        O[nt][3] *= alpha1;
      }

#pragma unroll
      for (int ks = 0; ks < 4; ks++) {
        const uint32_t a[4] = {f2h2(S[2 * ks][0], S[2 * ks][1]),
                               f2h2(S[2 * ks][2], S[2 * ks][3]),
                               f2h2(S[2 * ks + 1][0], S[2 * ks + 1][1]),
                               f2h2(S[2 * ks + 1][2], S[2 * ks + 1][3])};
#pragma unroll
        for (int nt = 0; nt < 16; nt++) {
          uint2 bf = Vf[(ks * 16 + nt) * 32 + l];
          const uint32_t b[2] = {bf.x, bf.y};
          mma_f16(O[nt], a, b);
        }
      }
    }
  }

  // ---- epilogue: normalize + write DIRECTLY as packed fp16 A-blob for wo ----
  // thread (w,l) ≡ packed entry (kt=2h+(nt>=8), s=(nt&7)>>1, m=w, l'=l)
  const float inv0 = 1.0f / l_i0;
  const float inv1 = 1.0f / l_i1;
  uint4* outp = Pout + (size_t)qb * 32 * 1024;  // 32 k-tiles per m-band
#pragma unroll
  for (int p = 0; p < 8; p++) {
    const int nt = 2 * p;
    const int kt = 2 * h + (nt >> 3);
    const int s = (nt & 7) >> 1;
    uint4 u;
    u.x = f2h2(O[nt][0] * inv0, O[nt][1] * inv0);
    u.y = f2h2(O[nt][2] * inv1, O[nt][3] * inv1);
    u.z = f2h2(O[nt + 1][0] * inv0, O[nt + 1][1] * inv0);
    u.w = f2h2(O[nt + 1][2] * inv1, O[nt + 1][3] * inv1);
    outp[(size_t)kt * 1024 + s * 256 + w * 32 + l] = u;
  }
}

// ---------------- launch ----------------------------------------------------
extern "C" void kernel_launch(void* const* d_in, const int* in_sizes, int n_in,
                              void* d_out, int out_size) {
  const float* x = (const float*)d_in[0];
  const float* wq = (const float*)d_in[1];
  const float* wk = (const float*)d_in[2];
  const float* wv = (const float*)d_in[3];
  const float* wo = (const float*)d_in[4];
  float* out = (float*)d_out;

  float* qkv_p;
  uint4 *pa, *pattn;
  uint2 *pbqkv, *pbwo;
  cudaGetSymbolAddress((void**)&qkv_p, g_qkv);
  cudaGetSymbolAddress((void**)&pa, g_pa);
  cudaGetSymbolAddress((void**)&pattn, g_pattn);
  cudaGetSymbolAddress((void**)&pbqkv, g_pbqkv);
  cudaGetSymbolAddress((void**)&pbwo, g_pbwo);

  cudaFuncSetAttribute(gemm_f16, cudaFuncAttributeMaxDynamicSharedMemorySize,
                       GEMM_SMEM);
  cudaFuncSetAttribute(flash_f16_kernel,
                       cudaFuncAttributeMaxDynamicSharedMemorySize,
                       F_SMEM_BYTES);

  // rope table + operand packing
  rope_table_kernel<<<(S_LEN * 64) / 256, 256>>>();
  pack_a_f16<<<dim3(DM / 64, S_LEN / 128), 256>>>(x, pa, DM);
  pack_b_f16<<<dim3(DM / 64, 16), 256>>>(wq, pbqkv, DM, 0);
  pack_b_f16<<<dim3(DM / 64, 4), 256>>>(wk, pbqkv, NKV * HD, 16);
  pack_b_f16<<<dim3(DM / 64, 4), 256>>>(wv, pbqkv, NKV * HD, 20);
  pack_b_f16<<<dim3(DM / 64, 16), 256>>>(wo, pbwo, DM, 0);

  // fused QKV projection: [4096,2048] x [2048,3072]
  gemm_f16<<<dim3(QKVW / 128, S_LEN / 128), 256, GEMM_SMEM>>>(pa, pbqkv, qkv_p,
                                                              QKVW, DM);

  // RoPE apply (table-driven)
  rope_apply_kernel<<<dim3(S_LEN / 4, NH + NKV), 256>>>(qkv_p);

  // causal flash attention (fp16 mma, packed-out epilogue)
  flash_f16_kernel<<<dim3(S_LEN / BQ, NH), 256, F_SMEM_BYTES>>>(qkv_p, pattn);

  // output projection (reads flash's packed output directly)
  gemm_f16<<<dim3(DM / 128, S_LEN / 128), 256, GEMM_SMEM>>>(pattn, pbwo, out,
                                                            DM, DM);
}

// round 9
// speedup vs baseline: 8.4800x; 1.3429x over previous
#include <cuda_runtime.h>
#include <cuda_fp16.h>
#include <math.h>
#include <stdint.h>

#define S_LEN  4096
#define DM     2048
#define NH     16
#define NKV    4
#define HD     128
#define QKVW   3072          // fused qkv width

// ---------------- scratch (device globals; no runtime alloc allowed) --------
__device__ float g_qkv[(size_t)S_LEN * QKVW];          // 48 MB  q|k|v fused
__device__ uint4 g_pa[(size_t)S_LEN * DM / 8];         // packed x (fp16 A blobs)
__device__ uint4 g_pattn[(size_t)S_LEN * DM / 8];      // packed attn (A blobs)
__device__ uint2 g_pbqkv[(size_t)QKVW * DM / 4];       // packed wq|wk|wv
__device__ uint2 g_pbwo[(size_t)DM * DM / 4];          // packed wo
__device__ float2 g_rope[(size_t)S_LEN * 64];          // cos/sin table
__device__ uint2 g_kf[(size_t)NKV * 64 * 2048];        // packed K frag blobs (4MB)
__device__ uint2 g_vf[(size_t)NKV * 64 * 2048];        // packed V frag blobs (4MB)

// ---------------- helpers ----------------------------------------------------
__device__ __forceinline__ uint32_t f2h2(float a, float b) {
  __half2 h = __floats2half2_rn(a, b);   // x=a (low), y=b (high)
  return *(uint32_t*)&h;
}

__device__ __forceinline__ void mma_f16(float* c, const uint32_t* a,
                                        const uint32_t* b) {
  asm volatile(
      "mma.sync.aligned.m16n8k16.row.col.f32.f16.f16.f32 "
      "{%0,%1,%2,%3}, {%4,%5,%6,%7}, {%8,%9}, {%0,%1,%2,%3};"
      : "+f"(c[0]), "+f"(c[1]), "+f"(c[2]), "+f"(c[3])
      : "r"(a[0]), "r"(a[1]), "r"(a[2]), "r"(a[3]), "r"(b[0]), "r"(b[1]));
}

__device__ __forceinline__ void cp16(uint32_t s, const void* g) {
  asm volatile("cp.async.cg.shared.global [%0], [%1], 16;" ::"r"(s), "l"(g));
}

__device__ __forceinline__ uint32_t smem_u32(const void* p) {
  uint32_t a;
  asm("{ .reg .u64 t; cvta.to.shared.u64 t, %1; cvt.u32.u64 %0, t; }"
      : "=r"(a) : "l"(p));
  return a;
}

// ---------------- fp16 pack kernels -----------------------------------------
__global__ __launch_bounds__(256) void pack_a_f16(const float* __restrict__ A,
                                                  uint4* __restrict__ P, int K) {
  const int kt = blockIdx.x, mb = blockIdx.y, tid = threadIdx.x;
  const int T = gridDim.x;
  uint4* out = P + ((size_t)mb * T + kt) * 1024;
#pragma unroll
  for (int idx = tid; idx < 1024; idx += 256) {
    const int s = idx >> 8, m = (idx >> 5) & 7, l = idx & 31;
    const int g = l >> 2, t = l & 3;
    const int row0 = mb * 128 + m * 16 + g;
    const int kb = kt * 64 + s * 16 + 2 * t;
    const float* r0 = A + (size_t)row0 * K + kb;
    const float* r1 = r0 + (size_t)8 * K;
    uint4 u;
    u.x = f2h2(r0[0], r0[1]);
    u.y = f2h2(r1[0], r1[1]);
    u.z = f2h2(r0[8], r0[9]);
    u.w = f2h2(r1[8], r1[9]);
    out[idx] = u;
  }
}

__global__ __launch_bounds__(256) void pack_b_f16(const float* __restrict__ W,
                                                  uint2* __restrict__ P, int Nin,
                                                  int noff) {
  const int kt = blockIdx.x, nb = blockIdx.y, tid = threadIdx.x;
  const int T = gridDim.x;
  uint2* out = P + ((size_t)(nb + noff) * T + kt) * 2048;
#pragma unroll
  for (int idx = tid; idx < 2048; idx += 256) {
    const int s = idx >> 9, n = (idx >> 5) & 15, l = idx & 31;
    const int t = l & 3;
    const int c = nb * 128 + n * 8 + (l >> 2);
    const int kb = kt * 64 + s * 16 + 2 * t;
    const float* w0 = W + (size_t)kb * Nin + c;
    uint2 u;
    u.x = f2h2(w0[0], w0[Nin]);
    u.y = f2h2(w0[(size_t)8 * Nin], w0[(size_t)9 * Nin]);
    out[idx] = u;
  }
}

// pack roped K and V into flash fragment blobs, once per (kvh, kv-tile)
__global__ __launch_bounds__(256) void pack_kv(const float* __restrict__ qkv) {
  const int t = blockIdx.x;    // kv tile 0..63
  const int kvh = blockIdx.y;  // 0..3
  const int tid = threadIdx.x;
  const float* Kp = qkv + DM + kvh * HD;
  const float* Vp = qkv + DM + NKV * HD + kvh * HD;
  uint2* ko = g_kf + ((size_t)kvh * 64 + t) * 2048;
  uint2* vo = g_vf + ((size_t)kvh * 64 + t) * 2048;
#pragma unroll
  for (int e = tid; e < 2048; e += 256) {
    const int l = e & 31, g = l >> 2, tt = l & 3;
    // K entry (ks=e>>8, nt=(e>>5)&7, l)
    {
      const int nt = (e >> 5) & 7, ks = e >> 8;
      const float* kr = Kp + (size_t)(t * 64 + 8 * nt + g) * QKVW + 16 * ks + 2 * tt;
      uint2 u;
      u.x = f2h2(kr[0], kr[1]);
      u.y = f2h2(kr[8], kr[9]);
      ko[e] = u;
    }
    // V entry (ks=e>>9, nt=(e>>5)&15, l)
    {
      const int nt = (e >> 5) & 15, ks = e >> 9;
      const int d = nt * 8 + g;
      const float* vr = Vp + (size_t)(t * 64 + ks * 16 + 2 * tt) * QKVW + d;
      uint2 u;
      u.x = f2h2(vr[0], vr[QKVW]);
      u.y = f2h2(vr[(size_t)8 * QKVW], vr[(size_t)9 * QKVW]);
      vo[e] = u;
    }
  }
}

// ---------------- packed fp16 GEMM: 2-stage (3 CTA/SM), 1 sync/iter ---------
#define GEMM_SMEM (2 * 32768)
__global__ __launch_bounds__(256) void gemm_f16(const uint4* __restrict__ Ap,
                                                const uint2* __restrict__ Bp,
                                                float* __restrict__ C, int N,
                                                int K) {
  extern __shared__ uint32_t sm[];
  const int tid = threadIdx.x;
  const int l = tid & 31;
  const int w = tid >> 5;
  const int warp_m = w >> 2;
  const int warp_n = w & 3;
  const int T = K >> 6;

  const uint4* Ag = Ap + (size_t)blockIdx.y * T * 1024;
  const uint4* Bg = (const uint4*)(Bp + (size_t)blockIdx.x * T * 2048);
  const uint32_t smu = smem_u32(sm);

  float acc[4][4][4];
#pragma unroll
  for (int mt = 0; mt < 4; mt++)
#pragma unroll
    for (int nt = 0; nt < 4; nt++)
#pragma unroll
      for (int c = 0; c < 4; c++) acc[mt][nt][c] = 0.0f;

#define CPT(t)                                                                 \
  do {                                                                         \
    const uint32_t ba = smu + ((t) & 1) * 32768;                               \
    const uint4* ga = Ag + (size_t)(t) * 1024;                                 \
    const uint4* gb = Bg + (size_t)(t) * 1024;                                 \
    _Pragma("unroll") for (int j = 0; j < 4; j++) {                            \
      cp16(ba + (tid + 256 * j) * 16, ga + tid + 256 * j);                     \
      cp16(ba + 16384 + (tid + 256 * j) * 16, gb + tid + 256 * j);             \
    }                                                                          \
    asm volatile("cp.async.commit_group;");                                    \
  } while (0)

  CPT(0);

  for (int t = 0; t < T; t++) {
    asm volatile("cp.async.wait_group 0;");
    __syncthreads();            // stage t ready; all warps done with stage t-1
    if (t + 1 < T) CPT(t + 1);  // overlaps compute(t); WAR safe via sync above

    const uint4* smA = (const uint4*)(sm + (t & 1) * 8192);
    const uint2* smB = (const uint2*)(sm + (t & 1) * 8192 + 4096);
#pragma unroll
    for (int s = 0; s < 4; s++) {
      uint4 af[4];
      uint2 bf[4];
#pragma unroll
      for (int mt = 0; mt < 4; mt++)
        af[mt] = smA[(s * 8 + warp_m * 4 + mt) * 32 + l];
#pragma unroll
      for (int nt = 0; nt < 4; nt++)
        bf[nt] = smB[(s * 16 + warp_n * 4 + nt) * 32 + l];
#pragma unroll
      for (int mt = 0; mt < 4; mt++) {
        const uint32_t a[4] = {af[mt].x, af[mt].y, af[mt].z, af[mt].w};
#pragma unroll
        for (int nt = 0; nt < 4; nt++) {
          const uint32_t b[2] = {bf[nt].x, bf[nt].y};
          mma_f16(acc[mt][nt], a, b);
        }
      }
    }
  }

  const int bm = blockIdx.y * 128;
  const int bn = blockIdx.x * 128;
#pragma unroll
  for (int mt = 0; mt < 4; mt++) {
    const int row = bm + warp_m * 64 + mt * 16 + (l >> 2);
#pragma unroll
    for (int nt = 0; nt < 4; nt++) {
      const int col = bn + warp_n * 32 + nt * 8 + 2 * (l & 3);
      float2 lo = {acc[mt][nt][0], acc[mt][nt][1]};
      float2 hi = {acc[mt][nt][2], acc[mt][nt][3]};
      *(float2*)(C + (size_t)row * N + col) = lo;
      *(float2*)(C + (size_t)(row + 8) * N + col) = hi;
    }
  }
}

// ---------------- RoPE: table + apply ----------------------------------------
__global__ __launch_bounds__(256) void rope_table_kernel() {
  const int idx = blockIdx.x * 256 + threadIdx.x;
  const int s = idx >> 6, d = idx & 63;
  float inv = powf(10000.0f, -((float)(2 * d) / 128.0f));
  float sn, cs;
  sincosf((float)s * inv, &sn, &cs);
  g_rope[idx] = make_float2(cs, sn);
}

__global__ __launch_bounds__(256) void rope_apply_kernel(float* __restrict__ qkv) {
  const int tid = threadIdx.x;
  const int d = tid & 63, si = tid >> 6;
  const int s = blockIdx.x * 4 + si;
  const int hh = blockIdx.y;
  float* ptr = qkv + (size_t)s * QKVW +
               (hh < NH ? hh * HD : DM + (hh - NH) * HD);
  const float2 cs = g_rope[s * 64 + d];
  const float x0 = ptr[d];
  const float x1 = ptr[d + 64];
  ptr[d] = x0 * cs.x - x1 * cs.y;
  ptr[d + 64] = x1 * cs.x + x0 * cs.y;
}

// ---------------- Flash attention, fp16 m16n8k16, cp.async KV pipeline ------
// Smem: Qf 32KB ; KV stages [2] x (K 16KB + V 16KB) = 64KB.  Total 96KB.
#define BQ 128
#define BKV 64
#define F_SMEM_BYTES (32768 + 2 * 32768)

__global__ __launch_bounds__(256) void flash_f16_kernel(
    const float* __restrict__ QKV, uint4* __restrict__ Pout) {
  extern __shared__ uint32_t fsm[];
  uint4* Qf = (uint4*)fsm;                 // 8192 words

  const int h = blockIdx.y;
  const int qb = gridDim.x - 1 - blockIdx.x;  // long blocks first
  const int q0 = qb * BQ;
  const int kvh = h >> 2;
  const int tid = threadIdx.x;
  const int l = tid & 31;
  const int w = tid >> 5;
  const int g = l >> 2;    // row group 0..7
  const int tt = l & 3;    // k/col group 0..3

  const float* Qp = QKV + h * HD;
  const float scale = 0.08838834764831845f;  // folded into Q
  const uint32_t smu = smem_u32(fsm);
  const uint4* kvbase_k = (const uint4*)(g_kf + (size_t)kvh * 64 * 2048);
  const uint4* kvbase_v = (const uint4*)(g_vf + (size_t)kvh * 64 * 2048);

#define CPKV(t)                                                                \
  do {                                                                         \
    const uint32_t ba = smu + 32768 + ((t) & 1) * 32768;                       \
    const uint4* kg = kvbase_k + (size_t)(t) * 1024;                           \
    const uint4* vg = kvbase_v + (size_t)(t) * 1024;                           \
    _Pragma("unroll") for (int j = 0; j < 4; j++) {                            \
      cp16(ba + (tid + 256 * j) * 16, kg + tid + 256 * j);                     \
      cp16(ba + 16384 + (tid + 256 * j) * 16, vg + tid + 256 * j);             \
    }                                                                          \
    asm volatile("cp.async.commit_group;");                                    \
  } while (0)

  CPKV(0);

  // ---- stage Q once (warp-private through smem; no sync needed) ----
#pragma unroll
  for (int i = 0; i < 8; i++) {
    const float* r0 = Qp + (size_t)(q0 + 16 * w + g) * QKVW + 16 * i + 2 * tt;
    const float* r1 = r0 + (size_t)8 * QKVW;
    float2 x0 = *(const float2*)r0;
    float2 x1 = *(const float2*)(r0 + 8);
    float2 y0 = *(const float2*)r1;
    float2 y1 = *(const float2*)(r1 + 8);
    uint4 u;
    u.x = f2h2(x0.x * scale, x0.y * scale);
    u.y = f2h2(y0.x * scale, y0.y * scale);
    u.z = f2h2(x1.x * scale, x1.y * scale);
    u.w = f2h2(y1.x * scale, y1.y * scale);
    Qf[tid + 256 * i] = u;
  }

  float m_i0 = -3.0e38f, m_i1 = -3.0e38f;
  float l_i0 = 0.0f, l_i1 = 0.0f;
  float O[16][4];
#pragma unroll
  for (int nt = 0; nt < 16; nt++)
#pragma unroll
    for (int c = 0; c < 4; c++) O[nt][c] = 0.0f;

  const int ntiles = (q0 + BQ) / BKV;

  for (int t = 0; t < ntiles; t++) {
    asm volatile("cp.async.wait_group 0;");
    __syncthreads();                  // stage t ready; all warps past t-1
    if (t + 1 < ntiles) CPKV(t + 1);  // overlaps compute(t)

    const uint2* Kf = (const uint2*)(fsm + 8192 + (t & 1) * 8192);
    const uint2* Vf = (const uint2*)(fsm + 8192 + (t & 1) * 8192 + 4096);

    const bool active = (t * BKV <= q0 + 16 * w + 15);
    if (active) {
      float S[8][4];
#pragma unroll
      for (int nt = 0; nt < 8; nt++)
#pragma unroll
        for (int c = 0; c < 4; c++) S[nt][c] = 0.0f;
#pragma unroll
      for (int ks = 0; ks < 8; ks++) {
        uint4 af = Qf[(ks * 8 + w) * 32 + l];
        const uint32_t a[4] = {af.x, af.y, af.z, af.w};
#pragma unroll
        for (int nt = 0; nt < 8; nt++) {
          uint2 bf = Kf[(ks * 8 + nt) * 32 + l];
          const uint32_t b[2] = {bf.x, bf.y};
          mma_f16(S[nt], a, b);
        }
      }

      const int rowg0 = q0 + 16 * w + g;
      const int rowg1 = rowg0 + 8;
      if (t * BKV + BKV - 1 > q0 + 16 * w) {
#pragma unroll
        for (int nt = 0; nt < 8; nt++) {
          const int c0 = t * BKV + nt * 8 + 2 * tt;
          if (c0 > rowg0) S[nt][0] = -3.0e38f;
          if (c0 + 1 > rowg0) S[nt][1] = -3.0e38f;
          if (c0 > rowg1) S[nt][2] = -3.0e38f;
          if (c0 + 1 > rowg1) S[nt][3] = -3.0e38f;
        }
      }

      float mx0 = -3.0e38f, mx1 = -3.0e38f;
#pragma unroll
      for (int nt = 0; nt < 8; nt++) {
        mx0 = fmaxf(mx0, fmaxf(S[nt][0], S[nt][1]));
        mx1 = fmaxf(mx1, fmaxf(S[nt][2], S[nt][3]));
      }
      mx0 = fmaxf(mx0, __shfl_xor_sync(0xffffffffu, mx0, 1));
      mx0 = fmaxf(mx0, __shfl_xor_sync(0xffffffffu, mx0, 2));
      mx1 = fmaxf(mx1, __shfl_xor_sync(0xffffffffu, mx1, 1));
      mx1 = fmaxf(mx1, __shfl_xor_sync(0xffffffffu, mx1, 2));
      const float mn0 = fmaxf(m_i0, mx0);
      const float mn1 = fmaxf(m_i1, mx1);

      float rs0 = 0.0f, rs1 = 0.0f;
#pragma unroll
      for (int nt = 0; nt < 8; nt++) {
        S[nt][0] = __expf(S[nt][0] - mn0);
        S[nt][1] = __expf(S[nt][1] - mn0);
        S[nt][2] = __expf(S[nt][2] - mn1);
        S[nt][3] = __expf(S[nt][3] - mn1);
        rs0 += S[nt][0] + S[nt][1];
        rs1 += S[nt][2] + S[nt][3];
      }
      rs0 += __shfl_xor_sync(0xffffffffu, rs0, 1);
      rs0 += __shfl_xor_sync(0xffffffffu, rs0, 2);
      rs1 += __shfl_xor_sync(0xffffffffu, rs1, 1);
      rs1 += __shfl_xor_sync(0xffffffffu, rs1, 2);
      const float alpha0 = __expf(m_i0 - mn0);
      const float alpha1 = __expf(m_i1 - mn1);
      l_i0 = l_i0 * alpha0 + rs0;
      l_i1 = l_i1 * alpha1 + rs1;
      m_i0 = mn0;
      m_i1 = mn1;
#pragma unroll
      for (int nt = 0; nt < 16; nt++) {
        O[nt][0] *= alpha0;
        O[nt][1] *= alpha0;
        O[nt][2] *= alpha1;
        O[nt][3] *= alpha1;
      }

#pragma unroll
      for (int ks = 0; ks < 4; ks++) {
        const uint32_t a[4] = {f2h2(S[2 * ks][0], S[2 * ks][1]),
                               f2h2(S[2 * ks][2], S[2 * ks][3]),
                               f2h2(S[2 * ks + 1][0], S[2 * ks + 1][1]),
                               f2h2(S[2 * ks + 1][2], S[2 * ks + 1][3])};
#pragma unroll
        for (int nt = 0; nt < 16; nt++) {
          uint2 bf = Vf[(ks * 16 + nt) * 32 + l];
          const uint32_t b[2] = {bf.x, bf.y};
          mma_f16(O[nt], a, b);
        }
      }
    }
    __syncthreads();  // all warps done reading stage t before CPKV(t+2)
  }

  // ---- epilogue: normalize + write packed fp16 A-blob for wo GEMM ----
  const float inv0 = 1.0f / l_i0;
  const float inv1 = 1.0f / l_i1;
  uint4* outp = Pout + (size_t)qb * 32 * 1024;
#pragma unroll
  for (int p = 0; p < 8; p++) {
    const int nt = 2 * p;
    const int kt = 2 * h + (nt >> 3);
    const int s = (nt & 7) >> 1;
    uint4 u;
    u.x = f2h2(O[nt][0] * inv0, O[nt][1] * inv0);
    u.y = f2h2(O[nt][2] * inv1, O[nt][3] * inv1);
    u.z = f2h2(O[nt + 1][0] * inv0, O[nt + 1][1] * inv0);
    u.w = f2h2(O[nt + 1][2] * inv1, O[nt + 1][3] * inv1);
    outp[(size_t)kt * 1024 + s * 256 + w * 32 + l] = u;
  }
}

// ---------------- launch ----------------------------------------------------
extern "C" void kernel_launch(void* const* d_in, const int* in_sizes, int n_in,
                              void* d_out, int out_size) {
  const float* x = (const float*)d_in[0];
  const float* wq = (const float*)d_in[1];
  const float* wk = (const float*)d_in[2];
  const float* wv = (const float*)d_in[3];
  const float* wo = (const float*)d_in[4];
  float* out = (float*)d_out;

  float* qkv_p;
  uint4 *pa, *pattn;
  uint2 *pbqkv, *pbwo;
  cudaGetSymbolAddress((void**)&qkv_p, g_qkv);
  cudaGetSymbolAddress((void**)&pa, g_pa);
  cudaGetSymbolAddress((void**)&pattn, g_pattn);
  cudaGetSymbolAddress((void**)&pbqkv, g_pbqkv);
  cudaGetSymbolAddress((void**)&pbwo, g_pbwo);

  cudaFuncSetAttribute(gemm_f16, cudaFuncAttributeMaxDynamicSharedMemorySize,
                       GEMM_SMEM);
  cudaFuncSetAttribute(flash_f16_kernel,
                       cudaFuncAttributeMaxDynamicSharedMemorySize,
                       F_SMEM_BYTES);

  // rope table + operand packing
  rope_table_kernel<<<(S_LEN * 64) / 256, 256>>>();
  pack_a_f16<<<dim3(DM / 64, S_LEN / 128), 256>>>(x, pa, DM);
  pack_b_f16<<<dim3(DM / 64, 16), 256>>>(wq, pbqkv, DM, 0);
  pack_b_f16<<<dim3(DM / 64, 4), 256>>>(wk, pbqkv, NKV * HD, 16);
  pack_b_f16<<<dim3(DM / 64, 4), 256>>>(wv, pbqkv, NKV * HD, 20);
  pack_b_f16<<<dim3(DM / 64, 16), 256>>>(wo, pbwo, DM, 0);

  // fused QKV projection: [4096,2048] x [2048,3072]
  gemm_f16<<<dim3(QKVW / 128, S_LEN / 128), 256, GEMM_SMEM>>>(pa, pbqkv, qkv_p,
                                                              QKVW, DM);

  // RoPE apply (table-driven, q and k)
  rope_apply_kernel<<<dim3(S_LEN / 4, NH + NKV), 256>>>(qkv_p);

  // pack roped K/V into fp16 fragment blobs (once)
  pack_kv<<<dim3(S_LEN / BKV, NKV), 256>>>(qkv_p);

  // causal flash attention (fp16 mma, cp.async KV pipeline, packed-out)
  flash_f16_kernel<<<dim3(S_LEN / BQ, NH), 256, F_SMEM_BYTES>>>(qkv_p, pattn);

  // output projection (reads flash's packed output directly)
  gemm_f16<<<dim3(DM / 128, S_LEN / 128), 256, GEMM_SMEM>>>(pattn, pbwo, out,
                                                            DM, DM);
}